// round 10
// baseline (speedup 1.0000x reference)
#include <cuda_runtime.h>
#include <cuda_fp16.h>
#include <cstdint>
#include <math.h>

#define Tt 512
#define Bb 32
#define Ee 512
#define Hh 256
#define Dd 512
#define DFFv 2048
#define Cc 16
#define Mm (Tt*Bb)

__device__ __forceinline__ uint32_t smem_u32(const void* p) {
    uint32_t a;
    asm("{ .reg .u64 t; cvta.to.shared.u64 t, %1; cvt.u32.u64 %0, t; }" : "=r"(a) : "l"(p));
    return a;
}
// fp32-accumulate HMMA (main term)
__device__ __forceinline__ void mma16816(float* c, const uint32_t* a, const uint32_t* b) {
    asm volatile("mma.sync.aligned.m16n8k16.row.col.f32.f16.f16.f32 "
        "{%0,%1,%2,%3}, {%4,%5,%6,%7}, {%8,%9}, {%0,%1,%2,%3};"
        : "+f"(c[0]), "+f"(c[1]), "+f"(c[2]), "+f"(c[3])
        : "r"(a[0]), "r"(a[1]), "r"(a[2]), "r"(a[3]), "r"(b[0]), "r"(b[1]));
}
// fp16-accumulate HMMA (cross terms; values small & zero-mean)
__device__ __forceinline__ void mma16816h(uint32_t* c, const uint32_t* a, const uint32_t* b) {
    asm volatile("mma.sync.aligned.m16n8k16.row.col.f16.f16.f16.f16 "
        "{%0,%1}, {%2,%3,%4,%5}, {%6,%7}, {%0,%1};"
        : "+r"(c[0]), "+r"(c[1])
        : "r"(a[0]), "r"(a[1]), "r"(a[2]), "r"(a[3]), "r"(b[0]), "r"(b[1]));
}
__device__ __forceinline__ void ldsm4(uint32_t* r, uint32_t addr) {
    asm volatile("ldmatrix.sync.aligned.m8n8.x4.shared.b16 {%0,%1,%2,%3}, [%4];"
        : "=r"(r[0]), "=r"(r[1]), "=r"(r[2]), "=r"(r[3]) : "r"(addr));
}
#define CP_ASYNC16(dst, src) \
    asm volatile("cp.async.cg.shared.global [%0], [%1], 16;" :: "r"(dst), "l"(src))
#define CP_COMMIT() asm volatile("cp.async.commit_group;")
#define CP_WAIT(n)  asm volatile("cp.async.wait_group %0;" :: "n"(n) : "memory")

__device__ __forceinline__ void split2h(float v, __half& h, __half& l) {
    h = __float2half_rn(v);
    l = __float2half_rn(v - __half2float(h));
}
__device__ __forceinline__ void red_release(unsigned* p, unsigned v) {
    asm volatile("red.release.gpu.global.add.u32 [%0], %1;" :: "l"(p), "r"(v) : "memory");
}
__device__ __forceinline__ unsigned ld_acquire(const unsigned* p) {
    unsigned v;
    asm volatile("ld.acquire.gpu.global.u32 %0, [%1];" : "=r"(v) : "l"(p) : "memory");
    return v;
}

// ======== scratch carve-out (float units, 64-aligned) ========
constexpr size_t AL64(size_t x) { return (x + 63) & ~(size_t)63; }
constexpr size_t SZ_GI = (size_t)Mm*3*Hh, SZ_HC = (size_t)Mm*Dd;
constexpr size_t SZ_LOG = (size_t)Mm*Cc, SZ_BPF = AL64(((size_t)(Tt-1)*Bb*Cc + 3)/4);
constexpr size_t SZ_H0S = (size_t)Mm*Ee/2, SZ_HCS = (size_t)Mm*Dd/2, SZ_MDS = (size_t)Mm*DFFv/2;
constexpr size_t SZ_W1S = (size_t)4*Dd*DFFv/2, SZ_W2S = (size_t)4*DFFv*Dd/2, SZ_WIS = (size_t)3*Hh*Ee/2;
constexpr size_t OFF_GI0 = 0;
constexpr size_t OFF_GI1 = AL64(OFF_GI0 + SZ_GI);
constexpr size_t OFF_HCAT= AL64(OFF_GI1 + SZ_GI);
constexpr size_t OFF_TMP = AL64(OFF_HCAT + SZ_HC);
constexpr size_t OFF_LOG = AL64(OFF_TMP + SZ_HC);
constexpr size_t OFF_BP  = AL64(OFF_LOG + SZ_LOG);
constexpr size_t OFF_CNT = AL64(OFF_BP + SZ_BPF);          // 1024 u32 reserved
constexpr size_t OFF_H0H = AL64(OFF_CNT + 1024);
constexpr size_t OFF_H0L = AL64(OFF_H0H + SZ_H0S);
constexpr size_t OFF_HCH = AL64(OFF_H0L + SZ_H0S);
constexpr size_t OFF_HCL = AL64(OFF_HCH + SZ_HCS);
constexpr size_t OFF_MDH = AL64(OFF_HCL + SZ_HCS);
constexpr size_t OFF_MDL = AL64(OFF_MDH + SZ_MDS);
constexpr size_t OFF_W1H = AL64(OFF_MDL + SZ_MDS);
constexpr size_t OFF_W1L = AL64(OFF_W1H + SZ_W1S);
constexpr size_t OFF_W2H = AL64(OFF_W1L + SZ_W1S);
constexpr size_t OFF_W2L = AL64(OFF_W2H + SZ_W2S);
constexpr size_t OFF_WFH = AL64(OFF_W2L + SZ_W2S);
constexpr size_t OFF_WFL = AL64(OFF_WFH + SZ_WIS);
constexpr size_t OFF_WBH = AL64(OFF_WFL + SZ_WIS);
constexpr size_t OFF_WBL = AL64(OFF_WBH + SZ_WIS);
constexpr size_t TOTAL_F = AL64(OFF_WBL + SZ_WIS);

__device__ __align__(256) float g_buf[TOTAL_F];

// ======== fused embedding + positional encoding -> 2-limb fp16 ========
__global__ __launch_bounds__(256)
void embed_pe_kernel(__half* __restrict__ oh, __half* __restrict__ ol,
                     const float* __restrict__ emb, const int* __restrict__ x) {
    __shared__ double divs[256];
    int tid = threadIdx.x;
    divs[tid] = exp(-log(10000.0) * (double)(2*tid) / (double)Ee);
    __syncthreads();
    int idx = blockIdx.x * blockDim.x + tid;
    if (idx >= Mm * (Ee/4)) return;
    int row = idx >> 7, e4 = idx & 127;
    int t = row >> 5, b = row & 31;
    int tok = x[(size_t)b*Tt + t];
    float4 ev = *(const float4*)(emb + (size_t)tok*Ee + e4*4);
    float v[4] = {ev.x, ev.y, ev.z, ev.w};
    const double TWO_PI = 6.283185307179586476925;
    #pragma unroll
    for (int q = 0; q < 4; ++q) {
        int e = e4*4 + q;
        double a = (double)t * divs[e >> 1];
        double k = floor(a * (1.0 / TWO_PI));
        float r = (float)(a - k * TWO_PI);
        float pv = (e & 1) ? cosf(r) : sinf(r);
        v[q] += pv;
    }
    size_t o = (size_t)row*Ee + e4*4;
    #pragma unroll
    for (int q = 0; q < 4; ++q) { __half h, l; split2h(v[q], h, l); oh[o+q] = h; ol[o+q] = l; }
}

// ======== elementwise fp32 -> 2 limbs ========
__global__ void conv2_kernel(const float* __restrict__ in, __half* __restrict__ oh,
                             __half* __restrict__ ol, int n4) {
    int idx = blockIdx.x * blockDim.x + threadIdx.x;
    if (idx >= n4) return;
    float4 v4 = *(const float4*)(in + (size_t)idx*4);
    float v[4] = {v4.x, v4.y, v4.z, v4.w};
    size_t o = (size_t)idx*4;
    #pragma unroll
    for (int q = 0; q < 4; ++q) { __half h, l; split2h(v[q], h, l); oh[o+q] = h; ol[o+q] = l; }
}

// ======== fp16 2-limb MMA GEMM v3 ========
// 128x128 block tile, 8 warps (warp tile 64x32), K-chunk 16, 4-stage cp.async,
// one barrier per chunk, 48B row stride (conflict-free ldmatrix).
// Main term fp32-acc HMMA; cross terms fp16-acc HMMA (rate test).
// EPI 0: +bias -> fp32 | 1: relu(+bias) -> 2-limb fp16 | 2: +bias+res -> fp32
#define ROWH 24
#define TILE_E (128*ROWH)
#define STAGE_E (4*TILE_E)
#define MMA_SMEM (4*STAGE_E*2)

template<int EPI>
__global__ __launch_bounds__(256, 1)
void mma_gemm(const __half* __restrict__ Ah, const __half* __restrict__ Al,
              const __half* __restrict__ Bh, const __half* __restrict__ Bl,
              const float* __restrict__ bias, const float* __restrict__ res,
              float* __restrict__ Cf, __half* __restrict__ Ch, __half* __restrict__ Cl,
              int M, int N, int K) {
    extern __shared__ __half sh[];
    int tid = threadIdx.x, lane = tid & 31, wid = tid >> 5;
    int m0 = blockIdx.y * 128, n0 = blockIdx.x * 128;
    int wrow = wid & 1, wcol = wid >> 1;          // wcol 0..3 (32 cols each)
    const __half* gp[4] = {Ah + (size_t)m0*K, Al + (size_t)m0*K,
                           Bh + (size_t)n0*K, Bl + (size_t)n0*K};
    uint32_t sbase = smem_u32(sh);
    int NC = K >> 4;

    float acc[4][4][4];
    uint32_t acch[4][4][2];
    #pragma unroll
    for (int a = 0; a < 4; ++a)
        #pragma unroll
        for (int b = 0; b < 4; ++b) {
            #pragma unroll
            for (int q = 0; q < 4; ++q) acc[a][b][q] = 0.f;
            acch[a][b][0] = 0u; acch[a][b][1] = 0u;
        }

    // prologue: stages 0..2 (1024 16B-copies per stage, 4 per thread)
    #pragma unroll
    for (int ps = 0; ps < 3; ++ps) {
        #pragma unroll
        for (int i = 0; i < 4; ++i) {
            int idx = tid + i*256;
            int arr = idx >> 8, rem = idx & 255;
            int r = rem >> 1, hf = rem & 1;
            uint32_t dst = sbase + (uint32_t)(ps*STAGE_E + arr*TILE_E + r*ROWH + hf*8)*2;
            CP_ASYNC16(dst, gp[arr] + (size_t)r*K + ps*16 + hf*8);
        }
        CP_COMMIT();
    }

    int arow_lo = wrow*64 + (lane & 15);
    uint32_t a_off = (uint32_t)(arow_lo*ROWH + (lane >> 4)*8)*2;
    int brow_lo = wcol*32 + ((lane >> 4) << 3) + (lane & 7);
    uint32_t b_off = (uint32_t)(brow_lo*ROWH + ((lane >> 3) & 1)*8)*2;

    for (int c = 0; c < NC; ++c) {
        if (c < NC - 2) { CP_WAIT(2); } else { CP_WAIT(0); }
        __syncthreads();
        if (c + 3 < NC) {
            int slot = (c + 3) & 3;
            #pragma unroll
            for (int i = 0; i < 4; ++i) {
                int idx = tid + i*256;
                int arr = idx >> 8, rem = idx & 255;
                int r = rem >> 1, hf = rem & 1;
                uint32_t dst = sbase + (uint32_t)(slot*STAGE_E + arr*TILE_E + r*ROWH + hf*8)*2;
                CP_ASYNC16(dst, gp[arr] + (size_t)r*K + (c+3)*16 + hf*8);
            }
            CP_COMMIT();
        }
        uint32_t stg = sbase + (uint32_t)((c & 3)*STAGE_E)*2;
        uint32_t ah[4][4], al[4][4], bh[2][4], bl[2][4];
        #pragma unroll
        for (int mt = 0; mt < 4; ++mt) {
            uint32_t off = stg + (uint32_t)(mt*16*ROWH)*2 + a_off;
            ldsm4(ah[mt], off);
            ldsm4(al[mt], off + (uint32_t)TILE_E*2);
        }
        #pragma unroll
        for (int pr = 0; pr < 2; ++pr) {
            uint32_t off = stg + (uint32_t)(2*TILE_E)*2 + (uint32_t)(pr*16*ROWH)*2 + b_off;
            ldsm4(bh[pr], off);
            ldsm4(bl[pr], off + (uint32_t)TILE_E*2);
        }
        #pragma unroll
        for (int mt = 0; mt < 4; ++mt)
            #pragma unroll
            for (int pr = 0; pr < 2; ++pr)
                #pragma unroll
                for (int sub = 0; sub < 2; ++sub) {
                    int nt = pr*2 + sub;
                    mma16816(acc[mt][nt], ah[mt], &bh[pr][2*sub]);
                    mma16816h(acch[mt][nt], ah[mt], &bl[pr][2*sub]);
                    mma16816h(acch[mt][nt], al[mt], &bh[pr][2*sub]);
                }
    }

    // epilogue: main + float(cross) + bias
    int group = lane >> 2, tig = lane & 3;
    #pragma unroll
    for (int mt = 0; mt < 4; ++mt)
        #pragma unroll
        for (int nt = 0; nt < 4; ++nt) {
            int r = m0 + wrow*64 + mt*16 + group;
            int cc = n0 + wcol*32 + nt*8 + tig*2;
            float b0 = bias[cc], b1 = bias[cc+1];
            #pragma unroll
            for (int half = 0; half < 2; ++half) {
                int rr = r + half*8;
                __half2 px = *(__half2*)&acch[mt][nt][half];
                float v0 = acc[mt][nt][half*2+0] + __low2float(px) + b0;
                float v1 = acc[mt][nt][half*2+1] + __high2float(px) + b1;
                if (EPI == 1) {
                    v0 = fmaxf(v0, 0.f); v1 = fmaxf(v1, 0.f);
                    __half h0, l0, h1, l1;
                    split2h(v0, h0, l0); split2h(v1, h1, l1);
                    *(__half2*)(Ch + (size_t)rr*N + cc) = __halves2half2(h0, h1);
                    *(__half2*)(Cl + (size_t)rr*N + cc) = __halves2half2(l0, l1);
                } else {
                    if (EPI == 2) {
                        float2 r2 = *(const float2*)(res + (size_t)rr*N + cc);
                        v0 += r2.x; v1 += r2.y;
                    }
                    float2 o; o.x = v0; o.y = v1;
                    *(float2*)(Cf + (size_t)rr*N + cc) = o;
                }
            }
        }
}

// ======== counter zeroing ========
__global__ void zero_cnt_kernel(unsigned* __restrict__ c) {
    c[blockIdx.x * blockDim.x + threadIdx.x] = 0u;
}

// ======== persistent bidirectional GRU + concurrent FF weight conversion ========
// CTAs 0..63: GRU (32 per direction). CTAs 64..191: transpose+split ff weights.
#define GRU_SMEM ((24*260 + 32*260) * 4)
__global__ __launch_bounds__(256)
void gru_persistent(const float* __restrict__ gi0, const float* __restrict__ gi1,
                    float* __restrict__ hcat,
                    __half* __restrict__ hch, __half* __restrict__ hcl,
                    const float* __restrict__ whhF, const float* __restrict__ whhB,
                    const float* __restrict__ bhhF, const float* __restrict__ bhhB,
                    unsigned* __restrict__ cnt,
                    const float* __restrict__ ff_w1, const float* __restrict__ ff_w2,
                    __half* __restrict__ w1h, __half* __restrict__ w1l,
                    __half* __restrict__ w2h, __half* __restrict__ w2l) {
    extern __shared__ float sm[];
    int tid = threadIdx.x;

    if (blockIdx.x >= 64) {
        // ---- FF weight transpose+split (runs concurrent with GRU) ----
        float* tsm = sm;                       // 32x33 floats
        int tx = tid & 31, ty8 = tid >> 5;     // 32 x 8
        int cid = blockIdx.x - 64;             // 0..127
        for (int tile = cid; tile < 8192; tile += 128) {
            int blk = tile >> 11;
            int rem = tile & 2047;
            const float* in; __half *oh, *ol; int R, C; int t2;
            if (rem < 1024) {
                size_t wo = (size_t)blk*Dd*DFFv;
                in = ff_w1 + wo; oh = w1h + wo; ol = w1l + wo;
                R = Dd; C = DFFv; t2 = rem;
            } else {
                size_t wo = (size_t)blk*DFFv*Dd;
                in = ff_w2 + wo; oh = w2h + wo; ol = w2l + wo;
                R = DFFv; C = Dd; t2 = rem - 1024;
            }
            int ntx = C >> 5;
            int c0 = (t2 % ntx) << 5, r0 = (t2 / ntx) << 5;
            #pragma unroll
            for (int i = 0; i < 32; i += 8)
                tsm[(ty8 + i)*33 + tx] = in[(size_t)(r0 + ty8 + i)*C + c0 + tx];
            __syncthreads();
            #pragma unroll
            for (int i = 0; i < 32; i += 8) {
                __half h, l;
                split2h(tsm[tx*33 + ty8 + i], h, l);
                size_t o = (size_t)(c0 + ty8 + i)*R + r0 + tx;
                oh[o] = h; ol[o] = l;
            }
            __syncthreads();
        }
        return;
    }

    // ---- GRU ----
    float* w_s = sm;
    float* h_s = sm + 24*260;
    int dir = blockIdx.x >> 5, cta = blockIdx.x & 31;
    const float* gi  = dir ? gi1  : gi0;
    const float* whh = dir ? whhB : whhF;
    const float* bhh = dir ? bhhB : bhhF;
    unsigned* mycnt = cnt + dir * Tt;
    int jbase = cta * 8;

    for (int i = tid; i < 24*64; i += 256) {
        int lr = i >> 6, k4 = i & 63;
        int jl = lr / 3, g = lr % 3;
        float4 wv = *(const float4*)(whh + (size_t)(g*Hh + jbase + jl)*Hh + k4*4);
        *(float4*)&w_s[lr*260 + k4*4] = wv;
    }
    int lane = tid & 31, w = tid >> 5;
    int b  = ((w & 3) << 3) | (lane & 7);
    int jl = ((w >> 2) << 2) | (lane >> 3);
    int j = jbase + jl;
    float brr = bhh[j], bz = bhh[256 + j], bn_ = bhh[512 + j];
    const float* wr = w_s + (jl*3 + 0)*260;
    const float* wz = w_s + (jl*3 + 1)*260;
    const float* wn = w_s + (jl*3 + 2)*260;
    __syncthreads();

    for (int s = 0; s < Tt; ++s) {
        int t = dir ? (Tt - 1 - s) : s;
        // hoist gi loads (independent of staged h)
        const float* gib = gi + (size_t)t*Bb*768 + (size_t)b*768;
        float g_r = gib[j], g_z = gib[256 + j], g_n = gib[512 + j];
        const float* hp = nullptr;
        if (s > 0)
            hp = dir ? (hcat + (size_t)(t+1)*Bb*Dd + Hh) : (hcat + (size_t)(t-1)*Bb*Dd);
        if (hp) {
            for (int i = tid; i < 32*64; i += 256) {
                int bb = i >> 6, k4 = i & 63;
                float4 hv = *(const float4*)(hp + (size_t)bb*Dd + k4*4);
                *(float4*)&h_s[bb*260 + k4*4] = hv;
            }
        } else {
            for (int i = tid; i < 32*260; i += 256) h_s[i] = 0.f;
        }
        __syncthreads();

        const float* hb = h_s + b*260;
        float ar = 0.f, az = 0.f, an = 0.f;
        #pragma unroll 8
        for (int k4 = 0; k4 < 64; ++k4) {
            float4 h4  = *(const float4*)(hb + k4*4);
            float4 w_r = *(const float4*)(wr + k4*4);
            float4 w_z = *(const float4*)(wz + k4*4);
            float4 w_n = *(const float4*)(wn + k4*4);
            ar += w_r.x*h4.x + w_r.y*h4.y + w_r.z*h4.z + w_r.w*h4.w;
            az += w_z.x*h4.x + w_z.y*h4.y + w_z.z*h4.z + w_z.w*h4.w;
            an += w_n.x*h4.x + w_n.y*h4.y + w_n.z*h4.z + w_n.w*h4.w;
        }
        float hprev_v = h_s[b*260 + j];
        float r = 1.f / (1.f + expf(-(g_r + ar + brr)));
        float z = 1.f / (1.f + expf(-(g_z + az + bz)));
        float n = tanhf(g_n + r*(an + bn_));
        float hv = (1.f - z)*n + z*hprev_v;
        size_t oo = (size_t)t*Bb*Dd + (size_t)b*Dd + dir*Hh + j;
        hcat[oo] = hv;
        __half hh, hl;
        split2h(hv, hh, hl);
        hch[oo] = hh; hcl[oo] = hl;

        __syncthreads();
        if (tid == 0) {
            red_release(mycnt + s, 1u);
            while (ld_acquire(mycnt + s) < 32u) { }
        }
        __syncthreads();
    }
}

// ======== LayerNorm + fused 2-limb split ========
__global__ __launch_bounds__(128)
void ln_split2_kernel(const float* __restrict__ in, float* __restrict__ out,
                      __half* __restrict__ oh, __half* __restrict__ ol,
                      const float* __restrict__ g, const float* __restrict__ bta) {
    int row = blockIdx.x, tid = threadIdx.x;
    __shared__ float red[4];
    float4 v = *(const float4*)(in + (size_t)row*Dd + tid*4);
    float s = v.x + v.y + v.z + v.w;
    #pragma unroll
    for (int o = 16; o; o >>= 1) s += __shfl_xor_sync(0xffffffffu, s, o);
    if ((tid & 31) == 0) red[tid >> 5] = s;
    __syncthreads();
    float mean = (red[0]+red[1]+red[2]+red[3]) * (1.f/512.f);
    float dx = v.x-mean, dy = v.y-mean, dz = v.z-mean, dw = v.w-mean;
    float q = dx*dx + dy*dy + dz*dz + dw*dw;
    #pragma unroll
    for (int o = 16; o; o >>= 1) q += __shfl_xor_sync(0xffffffffu, q, o);
    __syncthreads();
    if ((tid & 31) == 0) red[tid >> 5] = q;
    __syncthreads();
    float var = (red[0]+red[1]+red[2]+red[3]) * (1.f/512.f);
    float rs = rsqrtf(var + 1e-5f);
    float4 g4 = *(const float4*)(g   + tid*4);
    float4 b4 = *(const float4*)(bta + tid*4);
    float ov[4];
    ov[0] = dx*rs*g4.x + b4.x; ov[1] = dy*rs*g4.y + b4.y;
    ov[2] = dz*rs*g4.z + b4.z; ov[3] = dw*rs*g4.w + b4.w;
    *(float4*)(out + (size_t)row*Dd + tid*4) = *(float4*)ov;
    size_t o = (size_t)row*Dd + tid*4;
    #pragma unroll
    for (int qq = 0; qq < 4; ++qq) {
        __half h, l;
        split2h(ov[qq], h, l);
        oh[o+qq] = h; ol[o+qq] = l;
    }
}

// ======== FC ========
__global__ __launch_bounds__(256)
void fc_kernel(const float* __restrict__ A, const float* __restrict__ W,
               const float* __restrict__ bias, float* __restrict__ out) {
    __shared__ float Ws[Dd*Cc];
    int tid = threadIdx.x;
    for (int i = tid; i < Dd*Cc; i += 256) Ws[i] = W[i];
    __syncthreads();
    int r = tid >> 4, c = tid & 15;
    size_t row = (size_t)blockIdx.x*16 + r;
    const float* a = A + row*Dd;
    float acc = bias[c];
    #pragma unroll 4
    for (int k4 = 0; k4 < Dd/4; ++k4) {
        float4 av = *(const float4*)(a + k4*4);
        int kb = k4*4;
        acc += av.x*Ws[(kb+0)*Cc + c] + av.y*Ws[(kb+1)*Cc + c]
             + av.z*Ws[(kb+2)*Cc + c] + av.w*Ws[(kb+3)*Cc + c];
    }
    out[row*Cc + c] = acc;
}

// ======== Viterbi ========
__global__ __launch_bounds__(512)
void viterbi_kernel(const float* __restrict__ logits, const int* __restrict__ y,
                    const float* __restrict__ trans, unsigned char* __restrict__ bp,
                    float* __restrict__ out) {
    __shared__ float tr[16][17];
    __shared__ float sc[2][32][16];
    __shared__ unsigned char path[32][512];
    __shared__ int tag_s[32];
    int tid = threadIdx.x;
    int b = tid >> 4, c = tid & 15;
    if (tid < 256) tr[tid >> 4][tid & 15] = trans[tid];
    sc[0][b][c] = trans[16*1 + c] + logits[(size_t)b*16 + c];
    __syncthreads();
    int p = 0;
    for (int t = 1; t < Tt; ++t) {
        float e = logits[(size_t)t*512 + tid];
        float best = -1e30f; int arg = 0;
        #pragma unroll
        for (int pv = 0; pv < 16; ++pv) {
            float v = sc[p][b][pv] + tr[pv][c];
            if (v > best) { best = v; arg = pv; }
        }
        bool m = (y[(size_t)b*Tt + t] != 0);
        float nv = m ? (best + e) : sc[p][b][c];
        bp[(size_t)(t-1)*512 + tid] = (unsigned char)arg;
        sc[1-p][b][c] = nv;
        __syncthreads();
        p ^= 1;
    }
    float fin = sc[p][b][c] + trans[c*16 + 2];
    sc[1-p][b][c] = fin;
    __syncthreads();
    if (c == 0) {
        float best = sc[1-p][b][0]; int arg = 0;
        #pragma unroll
        for (int k = 1; k < 16; ++k) {
            float v = sc[1-p][b][k];
            if (v > best) { best = v; arg = k; }
        }
        out[b] = best;
        tag_s[b] = arg;
    }
    __syncthreads();
    if (tid < 32) {
        int bb = tid;
        int tag = tag_s[bb];
        for (int i = Tt - 2; i >= 0; --i) {
            path[bb][i+1] = (unsigned char)tag;
            if (y[(size_t)bb*Tt + i + 1] != 0)
                tag = bp[(size_t)i*512 + bb*16 + tag];
        }
        path[bb][0] = (unsigned char)tag;
    }
    __syncthreads();
    for (int i = tid; i < 32*512; i += 512)
        out[32 + i] = (float)path[i >> 9][i & 511];
}

// ======== launcher ========
extern "C" void kernel_launch(void* const* d_in, const int* in_sizes, int n_in,
                              void* d_out, int out_size) {
    const int*   x      = (const int*)d_in[0];
    const int*   y      = (const int*)d_in[1];
    const float* embedW = (const float*)d_in[2];
    const float* w_ih_f = (const float*)d_in[3];
    const float* w_hh_f = (const float*)d_in[4];
    const float* b_ih_f = (const float*)d_in[5];
    const float* b_hh_f = (const float*)d_in[6];
    const float* w_ih_b = (const float*)d_in[7];
    const float* w_hh_b = (const float*)d_in[8];
    const float* b_ih_b = (const float*)d_in[9];
    const float* b_hh_b = (const float*)d_in[10];
    const float* ff_w1  = (const float*)d_in[11];
    const float* ff_b1  = (const float*)d_in[12];
    const float* ff_w2  = (const float*)d_in[13];
    const float* ff_b2  = (const float*)d_in[14];
    const float* ln_g   = (const float*)d_in[15];
    const float* ln_b   = (const float*)d_in[16];
    const float* fc_w   = (const float*)d_in[17];
    const float* fc_b   = (const float*)d_in[18];
    const float* trans  = (const float*)d_in[19];
    float* out = (float*)d_out;

    float* buf = nullptr;
    cudaGetSymbolAddress((void**)&buf, g_buf);
    float* gi0   = buf + OFF_GI0;
    float* gi1   = buf + OFF_GI1;
    float* hcat  = buf + OFF_HCAT;
    float* tmp   = buf + OFF_TMP;
    float* logit = buf + OFF_LOG;
    unsigned char* bp = (unsigned char*)(buf + OFF_BP);
    unsigned* cnt = (unsigned*)(buf + OFF_CNT);
    __half* h0h = (__half*)(buf + OFF_H0H);
    __half* h0l = (__half*)(buf + OFF_H0L);
    __half* hch = (__half*)(buf + OFF_HCH);
    __half* hcl = (__half*)(buf + OFF_HCL);
    __half* mdh = (__half*)(buf + OFF_MDH);
    __half* mdl = (__half*)(buf + OFF_MDL);
    __half* w1h = (__half*)(buf + OFF_W1H);
    __half* w1l = (__half*)(buf + OFF_W1L);
    __half* w2h = (__half*)(buf + OFF_W2H);
    __half* w2l = (__half*)(buf + OFF_W2L);
    __half* wfh = (__half*)(buf + OFF_WFH);
    __half* wfl = (__half*)(buf + OFF_WFL);
    __half* wbh = (__half*)(buf + OFF_WBH);
    __half* wbl = (__half*)(buf + OFF_WBL);

    cudaFuncSetAttribute(gru_persistent, cudaFuncAttributeMaxDynamicSharedMemorySize, GRU_SMEM);
    cudaFuncSetAttribute(mma_gemm<0>, cudaFuncAttributeMaxDynamicSharedMemorySize, MMA_SMEM);
    cudaFuncSetAttribute(mma_gemm<1>, cudaFuncAttributeMaxDynamicSharedMemorySize, MMA_SMEM);
    cudaFuncSetAttribute(mma_gemm<2>, cudaFuncAttributeMaxDynamicSharedMemorySize, MMA_SMEM);

    embed_pe_kernel<<<(Mm*(Ee/4) + 255)/256, 256>>>(h0h, h0l, embedW, x);
    conv2_kernel<<<(768*Ee/4 + 255)/256, 256>>>(w_ih_f, wfh, wfl, 768*Ee/4);
    mma_gemm<0><<<dim3(768/128, Mm/128), 256, MMA_SMEM>>>(
        h0h, h0l, wfh, wfl, b_ih_f, nullptr, gi0, nullptr, nullptr, Mm, 768, Ee);
    conv2_kernel<<<(768*Ee/4 + 255)/256, 256>>>(w_ih_b, wbh, wbl, 768*Ee/4);
    mma_gemm<0><<<dim3(768/128, Mm/128), 256, MMA_SMEM>>>(
        h0h, h0l, wbh, wbl, b_ih_b, nullptr, gi1, nullptr, nullptr, Mm, 768, Ee);

    zero_cnt_kernel<<<4, 256>>>(cnt);
    // 64 GRU CTAs + 128 weight-conversion CTAs in one launch (concurrent)
    gru_persistent<<<192, 256, GRU_SMEM>>>(gi0, gi1, hcat, hch, hcl,
                                           w_hh_f, w_hh_b, b_hh_f, b_hh_b, cnt,
                                           ff_w1, ff_w2, w1h, w1l, w2h, w2l);

    for (int i = 0; i < 4; ++i) {
        size_t wo1 = (size_t)i*Dd*DFFv, wo2 = (size_t)i*DFFv*Dd;
        mma_gemm<1><<<dim3(DFFv/128, Mm/128), 256, MMA_SMEM>>>(
            hch, hcl, w1h + wo1, w1l + wo1, ff_b1 + (size_t)i*DFFv, nullptr,
            nullptr, mdh, mdl, Mm, DFFv, Dd);
        mma_gemm<2><<<dim3(Dd/128, Mm/128), 256, MMA_SMEM>>>(
            mdh, mdl, w2h + wo2, w2l + wo2, ff_b2 + (size_t)i*Dd, hcat,
            tmp, nullptr, nullptr, Mm, Dd, DFFv);
        ln_split2_kernel<<<Mm, 128>>>(tmp, hcat, hch, hcl,
                                      ln_g + (size_t)i*Dd, ln_b + (size_t)i*Dd);
    }

    fc_kernel<<<Mm/16, 256>>>(hcat, fc_w, fc_b, logit);
    viterbi_kernel<<<1, 512>>>(logit, y, trans, bp, out);
}

// round 11
// speedup vs baseline: 1.1584x; 1.1584x over previous
#include <cuda_runtime.h>
#include <cuda_fp16.h>
#include <cstdint>
#include <math.h>

#define Tt 512
#define Bb 32
#define Ee 512
#define Hh 256
#define Dd 512
#define DFFv 2048
#define Cc 16
#define Mm (Tt*Bb)

__device__ __forceinline__ uint32_t smem_u32(const void* p) {
    uint32_t a;
    asm("{ .reg .u64 t; cvta.to.shared.u64 t, %1; cvt.u32.u64 %0, t; }" : "=r"(a) : "l"(p));
    return a;
}
__device__ __forceinline__ void mma16816(float* c, const uint32_t* a, const uint32_t* b) {
    asm volatile("mma.sync.aligned.m16n8k16.row.col.f32.f16.f16.f32 "
        "{%0,%1,%2,%3}, {%4,%5,%6,%7}, {%8,%9}, {%0,%1,%2,%3};"
        : "+f"(c[0]), "+f"(c[1]), "+f"(c[2]), "+f"(c[3])
        : "r"(a[0]), "r"(a[1]), "r"(a[2]), "r"(a[3]), "r"(b[0]), "r"(b[1]));
}
__device__ __forceinline__ void ldsm4(uint32_t* r, uint32_t addr) {
    asm volatile("ldmatrix.sync.aligned.m8n8.x4.shared.b16 {%0,%1,%2,%3}, [%4];"
        : "=r"(r[0]), "=r"(r[1]), "=r"(r[2]), "=r"(r[3]) : "r"(addr));
}
__device__ __forceinline__ void ldsm2(uint32_t* r, uint32_t addr) {
    asm volatile("ldmatrix.sync.aligned.m8n8.x2.shared.b16 {%0,%1}, [%2];"
        : "=r"(r[0]), "=r"(r[1]) : "r"(addr));
}
#define CP_ASYNC16(dst, src) \
    asm volatile("cp.async.cg.shared.global [%0], [%1], 16;" :: "r"(dst), "l"(src))
#define CP_COMMIT() asm volatile("cp.async.commit_group;")
#define CP_WAIT(n)  asm volatile("cp.async.wait_group %0;" :: "n"(n) : "memory")

__device__ __forceinline__ void split2h(float v, __half& h, __half& l) {
    h = __float2half_rn(v);
    l = __float2half_rn(v - __half2float(h));
}
__device__ __forceinline__ void red_release(unsigned* p, unsigned v) {
    asm volatile("red.release.gpu.global.add.u32 [%0], %1;" :: "l"(p), "r"(v) : "memory");
}
__device__ __forceinline__ unsigned ld_acquire(const unsigned* p) {
    unsigned v;
    asm volatile("ld.acquire.gpu.global.u32 %0, [%1];" : "=r"(v) : "l"(p) : "memory");
    return v;
}

// ======== scratch carve-out ========
constexpr size_t AL64(size_t x) { return (x + 63) & ~(size_t)63; }
constexpr size_t SZ_GI = (size_t)Mm*3*Hh, SZ_HC = (size_t)Mm*Dd;
constexpr size_t SZ_LOG = (size_t)Mm*Cc, SZ_BPF = AL64(((size_t)(Tt-1)*Bb*Cc + 3)/4);
constexpr size_t SZ_H0S = (size_t)Mm*Ee/2, SZ_HCS = (size_t)Mm*Dd/2, SZ_MDS = (size_t)Mm*DFFv/2;
constexpr size_t SZ_W1S = (size_t)4*Dd*DFFv/2, SZ_W2S = (size_t)4*DFFv*Dd/2, SZ_WIS = (size_t)3*Hh*Ee/2;
constexpr size_t OFF_GI0 = 0;
constexpr size_t OFF_GI1 = AL64(OFF_GI0 + SZ_GI);
constexpr size_t OFF_HCAT= AL64(OFF_GI1 + SZ_GI);
constexpr size_t OFF_TMP = AL64(OFF_HCAT + SZ_HC);
constexpr size_t OFF_LOG = AL64(OFF_TMP + SZ_HC);
constexpr size_t OFF_BP  = AL64(OFF_LOG + SZ_LOG);
constexpr size_t OFF_CNT = AL64(OFF_BP + SZ_BPF);
constexpr size_t OFF_H0H = AL64(OFF_CNT + 1024);
constexpr size_t OFF_H0L = AL64(OFF_H0H + SZ_H0S);
constexpr size_t OFF_HCH = AL64(OFF_H0L + SZ_H0S);
constexpr size_t OFF_HCL = AL64(OFF_HCH + SZ_HCS);
constexpr size_t OFF_MDH = AL64(OFF_HCL + SZ_HCS);
constexpr size_t OFF_MDL = AL64(OFF_MDH + SZ_MDS);
constexpr size_t OFF_W1H = AL64(OFF_MDL + SZ_MDS);
constexpr size_t OFF_W1L = AL64(OFF_W1H + SZ_W1S);
constexpr size_t OFF_W2H = AL64(OFF_W1L + SZ_W1S);
constexpr size_t OFF_W2L = AL64(OFF_W2H + SZ_W2S);
constexpr size_t OFF_WFH = AL64(OFF_W2L + SZ_W2S);
constexpr size_t OFF_WFL = AL64(OFF_WFH + SZ_WIS);
constexpr size_t OFF_WBH = AL64(OFF_WFL + SZ_WIS);
constexpr size_t OFF_WBL = AL64(OFF_WBH + SZ_WIS);
constexpr size_t TOTAL_F = AL64(OFF_WBL + SZ_WIS);

__device__ __align__(256) float g_buf[TOTAL_F];

// ======== fused embedding + positional encoding -> 2-limb fp16 ========
__global__ __launch_bounds__(256)
void embed_pe_kernel(__half* __restrict__ oh, __half* __restrict__ ol,
                     const float* __restrict__ emb, const int* __restrict__ x) {
    __shared__ double divs[256];
    int tid = threadIdx.x;
    divs[tid] = exp(-log(10000.0) * (double)(2*tid) / (double)Ee);
    __syncthreads();
    int idx = blockIdx.x * blockDim.x + tid;
    if (idx >= Mm * (Ee/4)) return;
    int row = idx >> 7, e4 = idx & 127;
    int t = row >> 5, b = row & 31;
    int tok = x[(size_t)b*Tt + t];
    float4 ev = *(const float4*)(emb + (size_t)tok*Ee + e4*4);
    float v[4] = {ev.x, ev.y, ev.z, ev.w};
    const double TWO_PI = 6.283185307179586476925;
    #pragma unroll
    for (int q = 0; q < 4; ++q) {
        int e = e4*4 + q;
        double a = (double)t * divs[e >> 1];
        double k = floor(a * (1.0 / TWO_PI));
        float r = (float)(a - k * TWO_PI);
        float pv = (e & 1) ? cosf(r) : sinf(r);
        v[q] += pv;
    }
    size_t o = (size_t)row*Ee + e4*4;
    #pragma unroll
    for (int q = 0; q < 4; ++q) { __half h, l; split2h(v[q], h, l); oh[o+q] = h; ol[o+q] = l; }
}

// ======== elementwise fp32 -> 2 limbs ========
__global__ void conv2_kernel(const float* __restrict__ in, __half* __restrict__ oh,
                             __half* __restrict__ ol, int n4) {
    int idx = blockIdx.x * blockDim.x + threadIdx.x;
    if (idx >= n4) return;
    float4 v4 = *(const float4*)(in + (size_t)idx*4);
    float v[4] = {v4.x, v4.y, v4.z, v4.w};
    size_t o = (size_t)idx*4;
    #pragma unroll
    for (int q = 0; q < 4; ++q) { __half h, l; split2h(v[q], h, l); oh[o+q] = h; ol[o+q] = l; }
}

// ======== fp16 2-limb MMA GEMM (R6 proven config: 2-stage, 8 warps, 2 CTA/SM) ====
#define LDSH 40
#define TILE_H (128*LDSH)
#define STAGE_H (4*TILE_H)
#define MMA_SMEM (2*STAGE_H*2)

template<int EPI>
__global__ __launch_bounds__(256)
void mma_gemm(const __half* __restrict__ Ah, const __half* __restrict__ Al,
              const __half* __restrict__ Bh, const __half* __restrict__ Bl,
              const float* __restrict__ bias, const float* __restrict__ res,
              float* __restrict__ Cf, __half* __restrict__ Ch, __half* __restrict__ Cl,
              int M, int N, int K) {
    extern __shared__ __half sh[];
    int tid = threadIdx.x, lane = tid & 31, wid = tid >> 5;
    int m0 = blockIdx.y * 128, n0 = blockIdx.x * 128;
    int wrow = wid & 1, wcol = wid >> 1;
    const __half* gp[4] = {Ah + (size_t)m0*K, Al + (size_t)m0*K,
                           Bh + (size_t)n0*K, Bl + (size_t)n0*K};
    uint32_t sbase = smem_u32(sh);
    int NC = K >> 5;

    float acc[4][4][4];
    #pragma unroll
    for (int a = 0; a < 4; ++a)
        #pragma unroll
        for (int b = 0; b < 4; ++b)
            #pragma unroll
            for (int q = 0; q < 4; ++q) acc[a][b][q] = 0.f;

    {
        #pragma unroll
        for (int i = 0; i < 8; ++i) {
            int idx = tid + i*256;
            int arr = idx >> 9, r = (idx >> 2) & 127, v = idx & 3;
            uint32_t dst = sbase + (uint32_t)(arr*TILE_H + r*LDSH + v*8)*2;
            CP_ASYNC16(dst, gp[arr] + (size_t)r*K + v*8);
        }
        CP_COMMIT();
    }
    for (int c = 0; c < NC; ++c) {
        if (c + 1 < NC) {
            int s = (c+1) & 1;
            #pragma unroll
            for (int i = 0; i < 8; ++i) {
                int idx = tid + i*256;
                int arr = idx >> 9, r = (idx >> 2) & 127, v = idx & 3;
                uint32_t dst = sbase + (uint32_t)(s*STAGE_H + arr*TILE_H + r*LDSH + v*8)*2;
                CP_ASYNC16(dst, gp[arr] + (size_t)r*K + (c+1)*32 + v*8);
            }
            CP_COMMIT();
            CP_WAIT(1);
        } else {
            CP_WAIT(0);
        }
        __syncthreads();
        uint32_t stg = sbase + (uint32_t)((c & 1)*STAGE_H)*2;
        #pragma unroll
        for (int kh2 = 0; kh2 < 2; ++kh2) {
            int ks = kh2*16;
            uint32_t ah[4][4], al[4][4], bh[4][2], bl[4][2];
            #pragma unroll
            for (int mt = 0; mt < 4; ++mt) {
                int row = wrow*64 + mt*16 + (lane & 15);
                uint32_t off = (uint32_t)(row*LDSH + ks + (lane >> 4)*8)*2;
                ldsm4(ah[mt], stg + off);
                ldsm4(al[mt], stg + (uint32_t)TILE_H*2 + off);
            }
            #pragma unroll
            for (int nt = 0; nt < 4; ++nt) {
                int l4 = lane & 15;
                int nr = wcol*32 + nt*8 + (l4 & 7);
                uint32_t off = (uint32_t)(nr*LDSH + ks + (l4 >> 3)*8)*2;
                ldsm2(bh[nt], stg + (uint32_t)(2*TILE_H)*2 + off);
                ldsm2(bl[nt], stg + (uint32_t)(3*TILE_H)*2 + off);
            }
            #pragma unroll
            for (int mt = 0; mt < 4; ++mt)
                #pragma unroll
                for (int nt = 0; nt < 4; ++nt) {
                    mma16816(acc[mt][nt], ah[mt], bh[nt]);
                    mma16816(acc[mt][nt], ah[mt], bl[nt]);
                    mma16816(acc[mt][nt], al[mt], bh[nt]);
                }
        }
        __syncthreads();
    }

    int group = lane >> 2, tig = lane & 3;
    #pragma unroll
    for (int mt = 0; mt < 4; ++mt)
        #pragma unroll
        for (int nt = 0; nt < 4; ++nt) {
            int r = m0 + wrow*64 + mt*16 + group;
            int cc = n0 + wcol*32 + nt*8 + tig*2;
            float b0 = bias[cc], b1 = bias[cc+1];
            #pragma unroll
            for (int half = 0; half < 2; ++half) {
                int rr = r + half*8;
                float v0 = acc[mt][nt][half*2+0] + b0;
                float v1 = acc[mt][nt][half*2+1] + b1;
                if (EPI == 1) {
                    v0 = fmaxf(v0, 0.f); v1 = fmaxf(v1, 0.f);
                    __half h0, l0, h1, l1;
                    split2h(v0, h0, l0); split2h(v1, h1, l1);
                    *(__half2*)(Ch + (size_t)rr*N + cc) = __halves2half2(h0, h1);
                    *(__half2*)(Cl + (size_t)rr*N + cc) = __halves2half2(l0, l1);
                } else {
                    if (EPI == 2) {
                        float2 r2 = *(const float2*)(res + (size_t)rr*N + cc);
                        v0 += r2.x; v1 += r2.y;
                    }
                    float2 o; o.x = v0; o.y = v1;
                    *(float2*)(Cf + (size_t)rr*N + cc) = o;
                }
            }
        }
}

// ======== counter zeroing ========
__global__ void zero_cnt_kernel(unsigned* __restrict__ c) {
    c[blockIdx.x * blockDim.x + threadIdx.x] = 0u;
}

// ======== persistent GRU v3: 128 GRU CTAs (4 units, k-split 2) + 128 conv CTAs ===
// smem: w rows [12][260] (kh=1 at +132), h [32][260] (k>=128 at +132)
#define GRU_SMEM ((12*260 + 32*260) * 4)
__global__ __launch_bounds__(256)
void gru_persistent(const float* __restrict__ gi0, const float* __restrict__ gi1,
                    float* __restrict__ hcat,
                    __half* __restrict__ hch, __half* __restrict__ hcl,
                    const float* __restrict__ whhF, const float* __restrict__ whhB,
                    const float* __restrict__ bhhF, const float* __restrict__ bhhB,
                    unsigned* __restrict__ cnt,
                    const float* __restrict__ ff_w1, const float* __restrict__ ff_w2,
                    __half* __restrict__ w1h, __half* __restrict__ w1l,
                    __half* __restrict__ w2h, __half* __restrict__ w2l) {
    extern __shared__ float sm[];
    int tid = threadIdx.x;

    if (blockIdx.x >= 128) {
        // ---- FF weight transpose+split (concurrent) ----
        float* tsm = sm;
        int tx = tid & 31, ty8 = tid >> 5;
        int cid = blockIdx.x - 128;
        for (int tile = cid; tile < 8192; tile += 128) {
            int blk = tile >> 11, rem = tile & 2047;
            const float* in; __half *oh, *ol; int R, C, t2;
            if (rem < 1024) {
                size_t wo = (size_t)blk*Dd*DFFv;
                in = ff_w1 + wo; oh = w1h + wo; ol = w1l + wo;
                R = Dd; C = DFFv; t2 = rem;
            } else {
                size_t wo = (size_t)blk*DFFv*Dd;
                in = ff_w2 + wo; oh = w2h + wo; ol = w2l + wo;
                R = DFFv; C = Dd; t2 = rem - 1024;
            }
            int ntx = C >> 5;
            int c0 = (t2 % ntx) << 5, r0 = (t2 / ntx) << 5;
            #pragma unroll
            for (int i = 0; i < 32; i += 8)
                tsm[(ty8 + i)*33 + tx] = in[(size_t)(r0 + ty8 + i)*C + c0 + tx];
            __syncthreads();
            #pragma unroll
            for (int i = 0; i < 32; i += 8) {
                __half h, l;
                split2h(tsm[tx*33 + ty8 + i], h, l);
                size_t o = (size_t)(c0 + ty8 + i)*R + r0 + tx;
                oh[o] = h; ol[o] = l;
            }
            __syncthreads();
        }
        return;
    }

    // ---- GRU: 64 CTAs per direction, 4 units each ----
    float* w_s = sm;              // 12 rows x 260
    float* h_s = sm + 12*260;     // 32 b x 260
    int dir = blockIdx.x >> 6, cta = blockIdx.x & 63;
    const float* gi  = dir ? gi1  : gi0;
    const float* whh = dir ? whhB : whhF;
    const float* bhh = dir ? bhhB : bhhF;
    unsigned* mycnt = cnt + dir * Tt;
    int jbase = cta * 4;

    // stage 12 weight rows (4 units x 3 gates); k>=128 goes at +132
    for (int i = tid; i < 12*64; i += 256) {
        int lr = i >> 6, k4 = i & 63;
        int jl = lr / 3, g = lr % 3;
        float4 wv = *(const float4*)(whh + (size_t)(g*Hh + jbase + jl)*Hh + k4*4);
        int doff = (k4 >= 32) ? (132 + (k4-32)*4) : (k4*4);
        *(float4*)&w_s[lr*260 + doff] = wv;
    }
    int lane = tid & 31, w = tid >> 5;
    int kh = lane & 1;
    int b  = ((w & 3) << 3) | ((lane >> 1) & 7);
    int jl = ((w >> 2) << 1) | (lane >> 4);
    int j = jbase + jl;
    float brr = bhh[j], bz = bhh[256 + j], bn_ = bhh[512 + j];
    const float* wr = w_s + (jl*3 + 0)*260 + kh*132;
    const float* wz = w_s + (jl*3 + 1)*260 + kh*132;
    const float* wn = w_s + (jl*3 + 2)*260 + kh*132;
    int joff = (j < 128) ? j : (132 + j - 128);
    __syncthreads();

    for (int s = 0; s < Tt; ++s) {
        int t = dir ? (Tt - 1 - s) : s;
        const float* gib = gi + (size_t)t*Bb*768 + (size_t)b*768;
        float g_r = gib[j], g_z = gib[256 + j], g_n = gib[512 + j];
        const float* hp = nullptr;
        if (s > 0)
            hp = dir ? (hcat + (size_t)(t+1)*Bb*Dd + Hh) : (hcat + (size_t)(t-1)*Bb*Dd);
        if (hp) {
            for (int i = tid; i < 32*64; i += 256) {
                int bb = i >> 6, k4 = i & 63;
                float4 hv = *(const float4*)(hp + (size_t)bb*Dd + k4*4);
                int doff = (k4 >= 32) ? (132 + (k4-32)*4) : (k4*4);
                *(float4*)&h_s[bb*260 + doff] = hv;
            }
        } else {
            for (int i = tid; i < 32*260; i += 256) h_s[i] = 0.f;
        }
        __syncthreads();

        const float* hb = h_s + b*260 + kh*132;
        float ar = 0.f, az = 0.f, an = 0.f;
        #pragma unroll 8
        for (int k4 = 0; k4 < 32; ++k4) {
            float4 h4  = *(const float4*)(hb + k4*4);
            float4 w_r = *(const float4*)(wr + k4*4);
            float4 w_z = *(const float4*)(wz + k4*4);
            float4 w_n = *(const float4*)(wn + k4*4);
            ar += w_r.x*h4.x + w_r.y*h4.y + w_r.z*h4.z + w_r.w*h4.w;
            az += w_z.x*h4.x + w_z.y*h4.y + w_z.z*h4.z + w_z.w*h4.w;
            an += w_n.x*h4.x + w_n.y*h4.y + w_n.z*h4.z + w_n.w*h4.w;
        }
        // combine the two k-halves
        ar += __shfl_xor_sync(0xffffffffu, ar, 1);
        az += __shfl_xor_sync(0xffffffffu, az, 1);
        an += __shfl_xor_sync(0xffffffffu, an, 1);

        if (kh == 0) {
            float hprev_v = h_s[b*260 + joff];
            float r = 1.f / (1.f + expf(-(g_r + ar + brr)));
            float z = 1.f / (1.f + expf(-(g_z + az + bz)));
            float n = tanhf(g_n + r*(an + bn_));
            float hv = (1.f - z)*n + z*hprev_v;
            size_t oo = (size_t)t*Bb*Dd + (size_t)b*Dd + dir*Hh + j;
            hcat[oo] = hv;
            __half hh, hl;
            split2h(hv, hh, hl);
            hch[oo] = hh; hcl[oo] = hl;
        }

        __syncthreads();
        if (tid == 0) {
            red_release(mycnt + s, 1u);
            while (ld_acquire(mycnt + s) < 64u) { }
        }
        __syncthreads();
    }
}

// ======== LayerNorm + fused 2-limb split ========
__global__ __launch_bounds__(128)
void ln_split2_kernel(const float* __restrict__ in, float* __restrict__ out,
                      __half* __restrict__ oh, __half* __restrict__ ol,
                      const float* __restrict__ g, const float* __restrict__ bta) {
    int row = blockIdx.x, tid = threadIdx.x;
    __shared__ float red[4];
    float4 v = *(const float4*)(in + (size_t)row*Dd + tid*4);
    float s = v.x + v.y + v.z + v.w;
    #pragma unroll
    for (int o = 16; o; o >>= 1) s += __shfl_xor_sync(0xffffffffu, s, o);
    if ((tid & 31) == 0) red[tid >> 5] = s;
    __syncthreads();
    float mean = (red[0]+red[1]+red[2]+red[3]) * (1.f/512.f);
    float dx = v.x-mean, dy = v.y-mean, dz = v.z-mean, dw = v.w-mean;
    float q = dx*dx + dy*dy + dz*dz + dw*dw;
    #pragma unroll
    for (int o = 16; o; o >>= 1) q += __shfl_xor_sync(0xffffffffu, q, o);
    __syncthreads();
    if ((tid & 31) == 0) red[tid >> 5] = q;
    __syncthreads();
    float var = (red[0]+red[1]+red[2]+red[3]) * (1.f/512.f);
    float rs = rsqrtf(var + 1e-5f);
    float4 g4 = *(const float4*)(g   + tid*4);
    float4 b4 = *(const float4*)(bta + tid*4);
    float ov[4];
    ov[0] = dx*rs*g4.x + b4.x; ov[1] = dy*rs*g4.y + b4.y;
    ov[2] = dz*rs*g4.z + b4.z; ov[3] = dw*rs*g4.w + b4.w;
    *(float4*)(out + (size_t)row*Dd + tid*4) = *(float4*)ov;
    size_t o = (size_t)row*Dd + tid*4;
    #pragma unroll
    for (int qq = 0; qq < 4; ++qq) {
        __half h, l;
        split2h(ov[qq], h, l);
        oh[o+qq] = h; ol[o+qq] = l;
    }
}

// ======== FC ========
__global__ __launch_bounds__(256)
void fc_kernel(const float* __restrict__ A, const float* __restrict__ W,
               const float* __restrict__ bias, float* __restrict__ out) {
    __shared__ float Ws[Dd*Cc];
    int tid = threadIdx.x;
    for (int i = tid; i < Dd*Cc; i += 256) Ws[i] = W[i];
    __syncthreads();
    int r = tid >> 4, c = tid & 15;
    size_t row = (size_t)blockIdx.x*16 + r;
    const float* a = A + row*Dd;
    float acc = bias[c];
    #pragma unroll 4
    for (int k4 = 0; k4 < Dd/4; ++k4) {
        float4 av = *(const float4*)(a + k4*4);
        int kb = k4*4;
        acc += av.x*Ws[(kb+0)*Cc + c] + av.y*Ws[(kb+1)*Cc + c]
             + av.z*Ws[(kb+2)*Cc + c] + av.w*Ws[(kb+3)*Cc + c];
    }
    out[row*Cc + c] = acc;
}

// ======== Viterbi ========
__global__ __launch_bounds__(512)
void viterbi_kernel(const float* __restrict__ logits, const int* __restrict__ y,
                    const float* __restrict__ trans, unsigned char* __restrict__ bp,
                    float* __restrict__ out) {
    __shared__ float tr[16][17];
    __shared__ float sc[2][32][16];
    __shared__ unsigned char path[32][512];
    __shared__ int tag_s[32];
    int tid = threadIdx.x;
    int b = tid >> 4, c = tid & 15;
    if (tid < 256) tr[tid >> 4][tid & 15] = trans[tid];
    sc[0][b][c] = trans[16*1 + c] + logits[(size_t)b*16 + c];
    __syncthreads();
    int p = 0;
    for (int t = 1; t < Tt; ++t) {
        float e = logits[(size_t)t*512 + tid];
        float best = -1e30f; int arg = 0;
        #pragma unroll
        for (int pv = 0; pv < 16; ++pv) {
            float v = sc[p][b][pv] + tr[pv][c];
            if (v > best) { best = v; arg = pv; }
        }
        bool m = (y[(size_t)b*Tt + t] != 0);
        float nv = m ? (best + e) : sc[p][b][c];
        bp[(size_t)(t-1)*512 + tid] = (unsigned char)arg;
        sc[1-p][b][c] = nv;
        __syncthreads();
        p ^= 1;
    }
    float fin = sc[p][b][c] + trans[c*16 + 2];
    sc[1-p][b][c] = fin;
    __syncthreads();
    if (c == 0) {
        float best = sc[1-p][b][0]; int arg = 0;
        #pragma unroll
        for (int k = 1; k < 16; ++k) {
            float v = sc[1-p][b][k];
            if (v > best) { best = v; arg = k; }
        }
        out[b] = best;
        tag_s[b] = arg;
    }
    __syncthreads();
    if (tid < 32) {
        int bb = tid;
        int tag = tag_s[bb];
        for (int i = Tt - 2; i >= 0; --i) {
            path[bb][i+1] = (unsigned char)tag;
            if (y[(size_t)bb*Tt + i + 1] != 0)
                tag = bp[(size_t)i*512 + bb*16 + tag];
        }
        path[bb][0] = (unsigned char)tag;
    }
    __syncthreads();
    for (int i = tid; i < 32*512; i += 512)
        out[32 + i] = (float)path[i >> 9][i & 511];
}

// ======== launcher ========
extern "C" void kernel_launch(void* const* d_in, const int* in_sizes, int n_in,
                              void* d_out, int out_size) {
    const int*   x      = (const int*)d_in[0];
    const int*   y      = (const int*)d_in[1];
    const float* embedW = (const float*)d_in[2];
    const float* w_ih_f = (const float*)d_in[3];
    const float* w_hh_f = (const float*)d_in[4];
    const float* b_ih_f = (const float*)d_in[5];
    const float* b_hh_f = (const float*)d_in[6];
    const float* w_ih_b = (const float*)d_in[7];
    const float* w_hh_b = (const float*)d_in[8];
    const float* b_ih_b = (const float*)d_in[9];
    const float* b_hh_b = (const float*)d_in[10];
    const float* ff_w1  = (const float*)d_in[11];
    const float* ff_b1  = (const float*)d_in[12];
    const float* ff_w2  = (const float*)d_in[13];
    const float* ff_b2  = (const float*)d_in[14];
    const float* ln_g   = (const float*)d_in[15];
    const float* ln_b   = (const float*)d_in[16];
    const float* fc_w   = (const float*)d_in[17];
    const float* fc_b   = (const float*)d_in[18];
    const float* trans  = (const float*)d_in[19];
    float* out = (float*)d_out;

    float* buf = nullptr;
    cudaGetSymbolAddress((void**)&buf, g_buf);
    float* gi0   = buf + OFF_GI0;
    float* gi1   = buf + OFF_GI1;
    float* hcat  = buf + OFF_HCAT;
    float* tmp   = buf + OFF_TMP;
    float* logit = buf + OFF_LOG;
    unsigned char* bp = (unsigned char*)(buf + OFF_BP);
    unsigned* cnt = (unsigned*)(buf + OFF_CNT);
    __half* h0h = (__half*)(buf + OFF_H0H);
    __half* h0l = (__half*)(buf + OFF_H0L);
    __half* hch = (__half*)(buf + OFF_HCH);
    __half* hcl = (__half*)(buf + OFF_HCL);
    __half* mdh = (__half*)(buf + OFF_MDH);
    __half* mdl = (__half*)(buf + OFF_MDL);
    __half* w1h = (__half*)(buf + OFF_W1H);
    __half* w1l = (__half*)(buf + OFF_W1L);
    __half* w2h = (__half*)(buf + OFF_W2H);
    __half* w2l = (__half*)(buf + OFF_W2L);
    __half* wfh = (__half*)(buf + OFF_WFH);
    __half* wfl = (__half*)(buf + OFF_WFL);
    __half* wbh = (__half*)(buf + OFF_WBH);
    __half* wbl = (__half*)(buf + OFF_WBL);

    cudaFuncSetAttribute(gru_persistent, cudaFuncAttributeMaxDynamicSharedMemorySize, GRU_SMEM);
    cudaFuncSetAttribute(mma_gemm<0>, cudaFuncAttributeMaxDynamicSharedMemorySize, MMA_SMEM);
    cudaFuncSetAttribute(mma_gemm<1>, cudaFuncAttributeMaxDynamicSharedMemorySize, MMA_SMEM);
    cudaFuncSetAttribute(mma_gemm<2>, cudaFuncAttributeMaxDynamicSharedMemorySize, MMA_SMEM);

    embed_pe_kernel<<<(Mm*(Ee/4) + 255)/256, 256>>>(h0h, h0l, embedW, x);
    conv2_kernel<<<(768*Ee/4 + 255)/256, 256>>>(w_ih_f, wfh, wfl, 768*Ee/4);
    mma_gemm<0><<<dim3(768/128, Mm/128), 256, MMA_SMEM>>>(
        h0h, h0l, wfh, wfl, b_ih_f, nullptr, gi0, nullptr, nullptr, Mm, 768, Ee);
    conv2_kernel<<<(768*Ee/4 + 255)/256, 256>>>(w_ih_b, wbh, wbl, 768*Ee/4);
    mma_gemm<0><<<dim3(768/128, Mm/128), 256, MMA_SMEM>>>(
        h0h, h0l, wbh, wbl, b_ih_b, nullptr, gi1, nullptr, nullptr, Mm, 768, Ee);

    zero_cnt_kernel<<<4, 256>>>(cnt);
    gru_persistent<<<256, 256, GRU_SMEM>>>(gi0, gi1, hcat, hch, hcl,
                                           w_hh_f, w_hh_b, b_hh_f, b_hh_b, cnt,
                                           ff_w1, ff_w2, w1h, w1l, w2h, w2l);

    for (int i = 0; i < 4; ++i) {
        size_t wo1 = (size_t)i*Dd*DFFv, wo2 = (size_t)i*DFFv*Dd;
        mma_gemm<1><<<dim3(DFFv/128, Mm/128), 256, MMA_SMEM>>>(
            hch, hcl, w1h + wo1, w1l + wo1, ff_b1 + (size_t)i*DFFv, nullptr,
            nullptr, mdh, mdl, Mm, DFFv, Dd);
        mma_gemm<2><<<dim3(Dd/128, Mm/128), 256, MMA_SMEM>>>(
            mdh, mdl, w2h + wo2, w2l + wo2, ff_b2 + (size_t)i*Dd, hcat,
            tmp, nullptr, nullptr, Mm, Dd, DFFv);
        ln_split2_kernel<<<Mm, 128>>>(tmp, hcat, hch, hcl,
                                      ln_g + (size_t)i*Dd, ln_b + (size_t)i*Dd);
    }

    fc_kernel<<<Mm/16, 256>>>(hcat, fc_w, fc_b, logit);
    viterbi_kernel<<<1, 512>>>(logit, y, trans, bp, out);
}

// round 12
// speedup vs baseline: 1.1587x; 1.0002x over previous
#include <cuda_runtime.h>
#include <cuda_fp16.h>
#include <cstdint>
#include <math.h>

#define Tt 512
#define Bb 32
#define Ee 512
#define Hh 256
#define Dd 512
#define DFFv 2048
#define Cc 16
#define Mm (Tt*Bb)

__device__ __forceinline__ uint32_t smem_u32(const void* p) {
    uint32_t a;
    asm("{ .reg .u64 t; cvta.to.shared.u64 t, %1; cvt.u32.u64 %0, t; }" : "=r"(a) : "l"(p));
    return a;
}
__device__ __forceinline__ void mma16816(float* c, const uint32_t* a, const uint32_t* b) {
    asm volatile("mma.sync.aligned.m16n8k16.row.col.f32.f16.f16.f32 "
        "{%0,%1,%2,%3}, {%4,%5,%6,%7}, {%8,%9}, {%0,%1,%2,%3};"
        : "+f"(c[0]), "+f"(c[1]), "+f"(c[2]), "+f"(c[3])
        : "r"(a[0]), "r"(a[1]), "r"(a[2]), "r"(a[3]), "r"(b[0]), "r"(b[1]));
}
__device__ __forceinline__ void ldsm4(uint32_t* r, uint32_t addr) {
    asm volatile("ldmatrix.sync.aligned.m8n8.x4.shared.b16 {%0,%1,%2,%3}, [%4];"
        : "=r"(r[0]), "=r"(r[1]), "=r"(r[2]), "=r"(r[3]) : "r"(addr));
}
__device__ __forceinline__ void ldsm2(uint32_t* r, uint32_t addr) {
    asm volatile("ldmatrix.sync.aligned.m8n8.x2.shared.b16 {%0,%1}, [%2];"
        : "=r"(r[0]), "=r"(r[1]) : "r"(addr));
}
#define CP_ASYNC16(dst, src) \
    asm volatile("cp.async.cg.shared.global [%0], [%1], 16;" :: "r"(dst), "l"(src))
#define CP_COMMIT() asm volatile("cp.async.commit_group;")
#define CP_WAIT(n)  asm volatile("cp.async.wait_group %0;" :: "n"(n) : "memory")

__device__ __forceinline__ void split2h(float v, __half& h, __half& l) {
    h = __float2half_rn(v);
    l = __float2half_rn(v - __half2float(h));
}
__device__ __forceinline__ void red_release(unsigned* p, unsigned v) {
    asm volatile("red.release.gpu.global.add.u32 [%0], %1;" :: "l"(p), "r"(v) : "memory");
}
__device__ __forceinline__ unsigned ld_acquire(const unsigned* p) {
    unsigned v;
    asm volatile("ld.acquire.gpu.global.u32 %0, [%1];" : "=r"(v) : "l"(p) : "memory");
    return v;
}

// ======== scratch carve-out ========
constexpr size_t AL64(size_t x) { return (x + 63) & ~(size_t)63; }
constexpr size_t SZ_GI = (size_t)Mm*3*Hh, SZ_HC = (size_t)Mm*Dd;
constexpr size_t SZ_LOG = (size_t)Mm*Cc, SZ_BPF = AL64(((size_t)(Tt-1)*Bb*Cc + 3)/4);
constexpr size_t SZ_H0S = (size_t)Mm*Ee/2, SZ_HCS = (size_t)Mm*Dd/2, SZ_MDS = (size_t)Mm*DFFv/2;
constexpr size_t SZ_W1S = (size_t)4*Dd*DFFv/2, SZ_W2S = (size_t)4*DFFv*Dd/2, SZ_WIS = (size_t)3*Hh*Ee/2;
constexpr size_t OFF_GI0 = 0;
constexpr size_t OFF_GI1 = AL64(OFF_GI0 + SZ_GI);
constexpr size_t OFF_HCAT= AL64(OFF_GI1 + SZ_GI);
constexpr size_t OFF_TMP = AL64(OFF_HCAT + SZ_HC);
constexpr size_t OFF_LOG = AL64(OFF_TMP + SZ_HC);
constexpr size_t OFF_BP  = AL64(OFF_LOG + SZ_LOG);
constexpr size_t OFF_CNT = AL64(OFF_BP + SZ_BPF);
constexpr size_t OFF_H0H = AL64(OFF_CNT + 1024);
constexpr size_t OFF_H0L = AL64(OFF_H0H + SZ_H0S);
constexpr size_t OFF_HCH = AL64(OFF_H0L + SZ_H0S);
constexpr size_t OFF_HCL = AL64(OFF_HCH + SZ_HCS);
constexpr size_t OFF_MDH = AL64(OFF_HCL + SZ_HCS);
constexpr size_t OFF_MDL = AL64(OFF_MDH + SZ_MDS);
constexpr size_t OFF_W1H = AL64(OFF_MDL + SZ_MDS);
constexpr size_t OFF_W1L = AL64(OFF_W1H + SZ_W1S);
constexpr size_t OFF_W2H = AL64(OFF_W1L + SZ_W1S);
constexpr size_t OFF_W2L = AL64(OFF_W2H + SZ_W2S);
constexpr size_t OFF_WFH = AL64(OFF_W2L + SZ_W2S);
constexpr size_t OFF_WFL = AL64(OFF_WFH + SZ_WIS);
constexpr size_t OFF_WBH = AL64(OFF_WFL + SZ_WIS);
constexpr size_t OFF_WBL = AL64(OFF_WBH + SZ_WIS);
constexpr size_t TOTAL_F = AL64(OFF_WBL + SZ_WIS);

__device__ __align__(256) float g_buf[TOTAL_F];

// ======== fused embedding + positional encoding -> 2-limb fp16 ========
__global__ __launch_bounds__(256)
void embed_pe_kernel(__half* __restrict__ oh, __half* __restrict__ ol,
                     const float* __restrict__ emb, const int* __restrict__ x) {
    __shared__ double divs[256];
    int tid = threadIdx.x;
    divs[tid] = exp(-log(10000.0) * (double)(2*tid) / (double)Ee);
    __syncthreads();
    int idx = blockIdx.x * blockDim.x + tid;
    if (idx >= Mm * (Ee/4)) return;
    int row = idx >> 7, e4 = idx & 127;
    int t = row >> 5, b = row & 31;
    int tok = x[(size_t)b*Tt + t];
    float4 ev = *(const float4*)(emb + (size_t)tok*Ee + e4*4);
    float v[4] = {ev.x, ev.y, ev.z, ev.w};
    const double TWO_PI = 6.283185307179586476925;
    #pragma unroll
    for (int q = 0; q < 4; ++q) {
        int e = e4*4 + q;
        double a = (double)t * divs[e >> 1];
        double k = floor(a * (1.0 / TWO_PI));
        float r = (float)(a - k * TWO_PI);
        float pv = (e & 1) ? cosf(r) : sinf(r);
        v[q] += pv;
    }
    size_t o = (size_t)row*Ee + e4*4;
    #pragma unroll
    for (int q = 0; q < 4; ++q) { __half h, l; split2h(v[q], h, l); oh[o+q] = h; ol[o+q] = l; }
}

// ======== elementwise fp32 -> 2 limbs ========
__global__ void conv2_kernel(const float* __restrict__ in, __half* __restrict__ oh,
                             __half* __restrict__ ol, int n4) {
    int idx = blockIdx.x * blockDim.x + threadIdx.x;
    if (idx >= n4) return;
    float4 v4 = *(const float4*)(in + (size_t)idx*4);
    float v[4] = {v4.x, v4.y, v4.z, v4.w};
    size_t o = (size_t)idx*4;
    #pragma unroll
    for (int q = 0; q < 4; ++q) { __half h, l; split2h(v[q], h, l); oh[o+q] = h; ol[o+q] = l; }
}

// ======== fp16 2-limb MMA GEMM (limb-term-outer MMA ordering) ========
#define LDSH 40
#define TILE_H (128*LDSH)
#define STAGE_H (4*TILE_H)
#define MMA_SMEM (2*STAGE_H*2)

template<int EPI>
__global__ __launch_bounds__(256)
void mma_gemm(const __half* __restrict__ Ah, const __half* __restrict__ Al,
              const __half* __restrict__ Bh, const __half* __restrict__ Bl,
              const float* __restrict__ bias, const float* __restrict__ res,
              float* __restrict__ Cf, __half* __restrict__ Ch, __half* __restrict__ Cl,
              int M, int N, int K) {
    extern __shared__ __half sh[];
    int tid = threadIdx.x, lane = tid & 31, wid = tid >> 5;
    int m0 = blockIdx.y * 128, n0 = blockIdx.x * 128;
    int wrow = wid & 1, wcol = wid >> 1;
    const __half* gp[4] = {Ah + (size_t)m0*K, Al + (size_t)m0*K,
                           Bh + (size_t)n0*K, Bl + (size_t)n0*K};
    uint32_t sbase = smem_u32(sh);
    int NC = K >> 5;

    float acc[4][4][4];
    #pragma unroll
    for (int a = 0; a < 4; ++a)
        #pragma unroll
        for (int b = 0; b < 4; ++b)
            #pragma unroll
            for (int q = 0; q < 4; ++q) acc[a][b][q] = 0.f;

    {
        #pragma unroll
        for (int i = 0; i < 8; ++i) {
            int idx = tid + i*256;
            int arr = idx >> 9, r = (idx >> 2) & 127, v = idx & 3;
            uint32_t dst = sbase + (uint32_t)(arr*TILE_H + r*LDSH + v*8)*2;
            CP_ASYNC16(dst, gp[arr] + (size_t)r*K + v*8);
        }
        CP_COMMIT();
    }
    for (int c = 0; c < NC; ++c) {
        if (c + 1 < NC) {
            int s = (c+1) & 1;
            #pragma unroll
            for (int i = 0; i < 8; ++i) {
                int idx = tid + i*256;
                int arr = idx >> 9, r = (idx >> 2) & 127, v = idx & 3;
                uint32_t dst = sbase + (uint32_t)(s*STAGE_H + arr*TILE_H + r*LDSH + v*8)*2;
                CP_ASYNC16(dst, gp[arr] + (size_t)r*K + (c+1)*32 + v*8);
            }
            CP_COMMIT();
            CP_WAIT(1);
        } else {
            CP_WAIT(0);
        }
        __syncthreads();
        uint32_t stg = sbase + (uint32_t)((c & 1)*STAGE_H)*2;
        #pragma unroll
        for (int kh2 = 0; kh2 < 2; ++kh2) {
            int ks = kh2*16;
            uint32_t ah[4][4], al[4][4], bh[4][2], bl[4][2];
            #pragma unroll
            for (int mt = 0; mt < 4; ++mt) {
                int row = wrow*64 + mt*16 + (lane & 15);
                uint32_t off = (uint32_t)(row*LDSH + ks + (lane >> 4)*8)*2;
                ldsm4(ah[mt], stg + off);
                ldsm4(al[mt], stg + (uint32_t)TILE_H*2 + off);
            }
            #pragma unroll
            for (int nt = 0; nt < 4; ++nt) {
                int l4 = lane & 15;
                int nr = wcol*32 + nt*8 + (l4 & 7);
                uint32_t off = (uint32_t)(nr*LDSH + ks + (l4 >> 3)*8)*2;
                ldsm2(bh[nt], stg + (uint32_t)(2*TILE_H)*2 + off);
                ldsm2(bl[nt], stg + (uint32_t)(3*TILE_H)*2 + off);
            }
            // limb-term outermost: 16 independent accumulators between
            // successive touches of the same acc -> no RAW chain.
            #pragma unroll
            for (int mt = 0; mt < 4; ++mt)
                #pragma unroll
                for (int nt = 0; nt < 4; ++nt)
                    mma16816(acc[mt][nt], ah[mt], bh[nt]);
            #pragma unroll
            for (int mt = 0; mt < 4; ++mt)
                #pragma unroll
                for (int nt = 0; nt < 4; ++nt)
                    mma16816(acc[mt][nt], ah[mt], bl[nt]);
            #pragma unroll
            for (int mt = 0; mt < 4; ++mt)
                #pragma unroll
                for (int nt = 0; nt < 4; ++nt)
                    mma16816(acc[mt][nt], al[mt], bh[nt]);
        }
        __syncthreads();
    }

    int group = lane >> 2, tig = lane & 3;
    #pragma unroll
    for (int mt = 0; mt < 4; ++mt)
        #pragma unroll
        for (int nt = 0; nt < 4; ++nt) {
            int r = m0 + wrow*64 + mt*16 + group;
            int cc = n0 + wcol*32 + nt*8 + tig*2;
            float b0 = bias[cc], b1 = bias[cc+1];
            #pragma unroll
            for (int half = 0; half < 2; ++half) {
                int rr = r + half*8;
                float v0 = acc[mt][nt][half*2+0] + b0;
                float v1 = acc[mt][nt][half*2+1] + b1;
                if (EPI == 1) {
                    v0 = fmaxf(v0, 0.f); v1 = fmaxf(v1, 0.f);
                    __half h0, l0, h1, l1;
                    split2h(v0, h0, l0); split2h(v1, h1, l1);
                    *(__half2*)(Ch + (size_t)rr*N + cc) = __halves2half2(h0, h1);
                    *(__half2*)(Cl + (size_t)rr*N + cc) = __halves2half2(l0, l1);
                } else {
                    if (EPI == 2) {
                        float2 r2 = *(const float2*)(res + (size_t)rr*N + cc);
                        v0 += r2.x; v1 += r2.y;
                    }
                    float2 o; o.x = v0; o.y = v1;
                    *(float2*)(Cf + (size_t)rr*N + cc) = o;
                }
            }
        }
}

// ======== counter zeroing ========
__global__ void zero_cnt_kernel(unsigned* __restrict__ c) {
    c[blockIdx.x * blockDim.x + threadIdx.x] = 0u;
}

// ======== persistent GRU v4: 256 GRU CTAs (2 units, k-split 4) + 128 conv CTAs ===
// smem quarters padded: stride 272 floats/row, quarter offset 68 (16B aligned)
#define GRU_SMEM ((6*272 + 32*272) * 4)
__global__ __launch_bounds__(256)
void gru_persistent(const float* __restrict__ gi0, const float* __restrict__ gi1,
                    float* __restrict__ hcat,
                    __half* __restrict__ hch, __half* __restrict__ hcl,
                    const float* __restrict__ whhF, const float* __restrict__ whhB,
                    const float* __restrict__ bhhF, const float* __restrict__ bhhB,
                    unsigned* __restrict__ cnt,
                    const float* __restrict__ ff_w1, const float* __restrict__ ff_w2,
                    __half* __restrict__ w1h, __half* __restrict__ w1l,
                    __half* __restrict__ w2h, __half* __restrict__ w2l) {
    extern __shared__ float sm[];
    int tid = threadIdx.x;

    if (blockIdx.x >= 256) {
        // ---- FF weight transpose+split (concurrent) ----
        float* tsm = sm;
        int tx = tid & 31, ty8 = tid >> 5;
        int cid = blockIdx.x - 256;
        for (int tile = cid; tile < 8192; tile += 128) {
            int blk = tile >> 11, rem = tile & 2047;
            const float* in; __half *oh, *ol; int R, C, t2;
            if (rem < 1024) {
                size_t wo = (size_t)blk*Dd*DFFv;
                in = ff_w1 + wo; oh = w1h + wo; ol = w1l + wo;
                R = Dd; C = DFFv; t2 = rem;
            } else {
                size_t wo = (size_t)blk*DFFv*Dd;
                in = ff_w2 + wo; oh = w2h + wo; ol = w2l + wo;
                R = DFFv; C = Dd; t2 = rem - 1024;
            }
            int ntx = C >> 5;
            int c0 = (t2 % ntx) << 5, r0 = (t2 / ntx) << 5;
            #pragma unroll
            for (int i = 0; i < 32; i += 8)
                tsm[(ty8 + i)*33 + tx] = in[(size_t)(r0 + ty8 + i)*C + c0 + tx];
            __syncthreads();
            #pragma unroll
            for (int i = 0; i < 32; i += 8) {
                __half h, l;
                split2h(tsm[tx*33 + ty8 + i], h, l);
                size_t o = (size_t)(c0 + ty8 + i)*R + r0 + tx;
                oh[o] = h; ol[o] = l;
            }
            __syncthreads();
        }
        return;
    }

    // ---- GRU: 128 CTAs per direction, 2 units each, k-split 4 ----
    float* w_s = sm;              // 6 rows x 272
    float* h_s = sm + 6*272;      // 32 b x 272
    int dir = blockIdx.x >> 7, cta = blockIdx.x & 127;
    const float* gi  = dir ? gi1  : gi0;
    const float* whh = dir ? whhB : whhF;
    const float* bhh = dir ? bhhB : bhhF;
    unsigned* mycnt = cnt + dir * Tt;
    int jbase = cta * 2;

    // stage 6 weight rows (2 units x 3 gates), quarter layout
    for (int i = tid; i < 6*64; i += 256) {
        int lr = i >> 6, k4 = i & 63;
        int jl = lr / 3, g = lr % 3;
        float4 wv = *(const float4*)(whh + (size_t)(g*Hh + jbase + jl)*Hh + k4*4);
        *(float4*)&w_s[lr*272 + (k4 >> 4)*68 + (k4 & 15)*4] = wv;
    }
    int lane = tid & 31, w = tid >> 5;
    int kh = lane & 3;                          // k-quarter
    int b  = ((w & 3) << 3) | (lane >> 2);      // 0..31
    int jl = w >> 2;                            // 0..1
    int j = jbase + jl;
    float brr = bhh[j], bz = bhh[256 + j], bn_ = bhh[512 + j];
    const float* wr = w_s + (jl*3 + 0)*272 + kh*68;
    const float* wz = w_s + (jl*3 + 1)*272 + kh*68;
    const float* wn = w_s + (jl*3 + 2)*272 + kh*68;
    __syncthreads();

    for (int s = 0; s < Tt; ++s) {
        int t = dir ? (Tt - 1 - s) : s;
        const float* gib = gi + (size_t)t*Bb*768 + (size_t)b*768;
        float g_r = gib[j], g_z = gib[256 + j], g_n = gib[512 + j];
        const float* hp = nullptr;
        if (s > 0)
            hp = dir ? (hcat + (size_t)(t+1)*Bb*Dd + Hh) : (hcat + (size_t)(t-1)*Bb*Dd);
        if (hp) {
            for (int i = tid; i < 32*64; i += 256) {
                int bb = i >> 6, k4 = i & 63;
                float4 hv = *(const float4*)(hp + (size_t)bb*Dd + k4*4);
                *(float4*)&h_s[bb*272 + (k4 >> 4)*68 + (k4 & 15)*4] = hv;
            }
        } else {
            for (int i = tid; i < 32*272; i += 256) h_s[i] = 0.f;
        }
        __syncthreads();

        const float* hb = h_s + b*272 + kh*68;
        float ar = 0.f, az = 0.f, an = 0.f;
        #pragma unroll
        for (int k4 = 0; k4 < 16; ++k4) {
            float4 h4  = *(const float4*)(hb + k4*4);
            float4 w_r = *(const float4*)(wr + k4*4);
            float4 w_z = *(const float4*)(wz + k4*4);
            float4 w_n = *(const float4*)(wn + k4*4);
            ar += w_r.x*h4.x + w_r.y*h4.y + w_r.z*h4.z + w_r.w*h4.w;
            az += w_z.x*h4.x + w_z.y*h4.y + w_z.z*h4.z + w_z.w*h4.w;
            an += w_n.x*h4.x + w_n.y*h4.y + w_n.z*h4.z + w_n.w*h4.w;
        }
        // combine the four k-quarters
        ar += __shfl_xor_sync(0xffffffffu, ar, 1);
        az += __shfl_xor_sync(0xffffffffu, az, 1);
        an += __shfl_xor_sync(0xffffffffu, an, 1);
        ar += __shfl_xor_sync(0xffffffffu, ar, 2);
        az += __shfl_xor_sync(0xffffffffu, az, 2);
        an += __shfl_xor_sync(0xffffffffu, an, 2);

        if (kh == 0) {
            float hprev_v = h_s[b*272 + (j >> 6)*68 + (j & 63)];
            float r = 1.f / (1.f + expf(-(g_r + ar + brr)));
            float z = 1.f / (1.f + expf(-(g_z + az + bz)));
            float n = tanhf(g_n + r*(an + bn_));
            float hv = (1.f - z)*n + z*hprev_v;
            size_t oo = (size_t)t*Bb*Dd + (size_t)b*Dd + dir*Hh + j;
            hcat[oo] = hv;
            __half hh, hl;
            split2h(hv, hh, hl);
            hch[oo] = hh; hcl[oo] = hl;
        }

        __syncthreads();
        if (tid == 0) {
            red_release(mycnt + s, 1u);
            while (ld_acquire(mycnt + s) < 128u) { }
        }
        __syncthreads();
    }
}

// ======== LayerNorm + fused 2-limb split ========
__global__ __launch_bounds__(128)
void ln_split2_kernel(const float* __restrict__ in, float* __restrict__ out,
                      __half* __restrict__ oh, __half* __restrict__ ol,
                      const float* __restrict__ g, const float* __restrict__ bta) {
    int row = blockIdx.x, tid = threadIdx.x;
    __shared__ float red[4];
    float4 v = *(const float4*)(in + (size_t)row*Dd + tid*4);
    float s = v.x + v.y + v.z + v.w;
    #pragma unroll
    for (int o = 16; o; o >>= 1) s += __shfl_xor_sync(0xffffffffu, s, o);
    if ((tid & 31) == 0) red[tid >> 5] = s;
    __syncthreads();
    float mean = (red[0]+red[1]+red[2]+red[3]) * (1.f/512.f);
    float dx = v.x-mean, dy = v.y-mean, dz = v.z-mean, dw = v.w-mean;
    float q = dx*dx + dy*dy + dz*dz + dw*dw;
    #pragma unroll
    for (int o = 16; o; o >>= 1) q += __shfl_xor_sync(0xffffffffu, q, o);
    __syncthreads();
    if ((tid & 31) == 0) red[tid >> 5] = q;
    __syncthreads();
    float var = (red[0]+red[1]+red[2]+red[3]) * (1.f/512.f);
    float rs = rsqrtf(var + 1e-5f);
    float4 g4 = *(const float4*)(g   + tid*4);
    float4 b4 = *(const float4*)(bta + tid*4);
    float ov[4];
    ov[0] = dx*rs*g4.x + b4.x; ov[1] = dy*rs*g4.y + b4.y;
    ov[2] = dz*rs*g4.z + b4.z; ov[3] = dw*rs*g4.w + b4.w;
    *(float4*)(out + (size_t)row*Dd + tid*4) = *(float4*)ov;
    size_t o = (size_t)row*Dd + tid*4;
    #pragma unroll
    for (int qq = 0; qq < 4; ++qq) {
        __half h, l;
        split2h(ov[qq], h, l);
        oh[o+qq] = h; ol[o+qq] = l;
    }
}

// ======== FC ========
__global__ __launch_bounds__(256)
void fc_kernel(const float* __restrict__ A, const float* __restrict__ W,
               const float* __restrict__ bias, float* __restrict__ out) {
    __shared__ float Ws[Dd*Cc];
    int tid = threadIdx.x;
    for (int i = tid; i < Dd*Cc; i += 256) Ws[i] = W[i];
    __syncthreads();
    int r = tid >> 4, c = tid & 15;
    size_t row = (size_t)blockIdx.x*16 + r;
    const float* a = A + row*Dd;
    float acc = bias[c];
    #pragma unroll 4
    for (int k4 = 0; k4 < Dd/4; ++k4) {
        float4 av = *(const float4*)(a + k4*4);
        int kb = k4*4;
        acc += av.x*Ws[(kb+0)*Cc + c] + av.y*Ws[(kb+1)*Cc + c]
             + av.z*Ws[(kb+2)*Cc + c] + av.w*Ws[(kb+3)*Cc + c];
    }
    out[row*Cc + c] = acc;
}

// ======== Viterbi ========
__global__ __launch_bounds__(512)
void viterbi_kernel(const float* __restrict__ logits, const int* __restrict__ y,
                    const float* __restrict__ trans, unsigned char* __restrict__ bp,
                    float* __restrict__ out) {
    __shared__ float tr[16][17];
    __shared__ float sc[2][32][16];
    __shared__ unsigned char path[32][512];
    __shared__ int tag_s[32];
    int tid = threadIdx.x;
    int b = tid >> 4, c = tid & 15;
    if (tid < 256) tr[tid >> 4][tid & 15] = trans[tid];
    sc[0][b][c] = trans[16*1 + c] + logits[(size_t)b*16 + c];
    __syncthreads();
    int p = 0;
    for (int t = 1; t < Tt; ++t) {
        float e = logits[(size_t)t*512 + tid];
        float best = -1e30f; int arg = 0;
        #pragma unroll
        for (int pv = 0; pv < 16; ++pv) {
            float v = sc[p][b][pv] + tr[pv][c];
            if (v > best) { best = v; arg = pv; }
        }
        bool m = (y[(size_t)b*Tt + t] != 0);
        float nv = m ? (best + e) : sc[p][b][c];
        bp[(size_t)(t-1)*512 + tid] = (unsigned char)arg;
        sc[1-p][b][c] = nv;
        __syncthreads();
        p ^= 1;
    }
    float fin = sc[p][b][c] + trans[c*16 + 2];
    sc[1-p][b][c] = fin;
    __syncthreads();
    if (c == 0) {
        float best = sc[1-p][b][0]; int arg = 0;
        #pragma unroll
        for (int k = 1; k < 16; ++k) {
            float v = sc[1-p][b][k];
            if (v > best) { best = v; arg = k; }
        }
        out[b] = best;
        tag_s[b] = arg;
    }
    __syncthreads();
    if (tid < 32) {
        int bb = tid;
        int tag = tag_s[bb];
        for (int i = Tt - 2; i >= 0; --i) {
            path[bb][i+1] = (unsigned char)tag;
            if (y[(size_t)bb*Tt + i + 1] != 0)
                tag = bp[(size_t)i*512 + bb*16 + tag];
        }
        path[bb][0] = (unsigned char)tag;
    }
    __syncthreads();
    for (int i = tid; i < 32*512; i += 512)
        out[32 + i] = (float)path[i >> 9][i & 511];
}

// ======== launcher ========
extern "C" void kernel_launch(void* const* d_in, const int* in_sizes, int n_in,
                              void* d_out, int out_size) {
    const int*   x      = (const int*)d_in[0];
    const int*   y      = (const int*)d_in[1];
    const float* embedW = (const float*)d_in[2];
    const float* w_ih_f = (const float*)d_in[3];
    const float* w_hh_f = (const float*)d_in[4];
    const float* b_ih_f = (const float*)d_in[5];
    const float* b_hh_f = (const float*)d_in[6];
    const float* w_ih_b = (const float*)d_in[7];
    const float* w_hh_b = (const float*)d_in[8];
    const float* b_ih_b = (const float*)d_in[9];
    const float* b_hh_b = (const float*)d_in[10];
    const float* ff_w1  = (const float*)d_in[11];
    const float* ff_b1  = (const float*)d_in[12];
    const float* ff_w2  = (const float*)d_in[13];
    const float* ff_b2  = (const float*)d_in[14];
    const float* ln_g   = (const float*)d_in[15];
    const float* ln_b   = (const float*)d_in[16];
    const float* fc_w   = (const float*)d_in[17];
    const float* fc_b   = (const float*)d_in[18];
    const float* trans  = (const float*)d_in[19];
    float* out = (float*)d_out;

    float* buf = nullptr;
    cudaGetSymbolAddress((void**)&buf, g_buf);
    float* gi0   = buf + OFF_GI0;
    float* gi1   = buf + OFF_GI1;
    float* hcat  = buf + OFF_HCAT;
    float* tmp   = buf + OFF_TMP;
    float* logit = buf + OFF_LOG;
    unsigned char* bp = (unsigned char*)(buf + OFF_BP);
    unsigned* cnt = (unsigned*)(buf + OFF_CNT);
    __half* h0h = (__half*)(buf + OFF_H0H);
    __half* h0l = (__half*)(buf + OFF_H0L);
    __half* hch = (__half*)(buf + OFF_HCH);
    __half* hcl = (__half*)(buf + OFF_HCL);
    __half* mdh = (__half*)(buf + OFF_MDH);
    __half* mdl = (__half*)(buf + OFF_MDL);
    __half* w1h = (__half*)(buf + OFF_W1H);
    __half* w1l = (__half*)(buf + OFF_W1L);
    __half* w2h = (__half*)(buf + OFF_W2H);
    __half* w2l = (__half*)(buf + OFF_W2L);
    __half* wfh = (__half*)(buf + OFF_WFH);
    __half* wfl = (__half*)(buf + OFF_WFL);
    __half* wbh = (__half*)(buf + OFF_WBH);
    __half* wbl = (__half*)(buf + OFF_WBL);

    cudaFuncSetAttribute(gru_persistent, cudaFuncAttributeMaxDynamicSharedMemorySize, GRU_SMEM);
    cudaFuncSetAttribute(mma_gemm<0>, cudaFuncAttributeMaxDynamicSharedMemorySize, MMA_SMEM);
    cudaFuncSetAttribute(mma_gemm<1>, cudaFuncAttributeMaxDynamicSharedMemorySize, MMA_SMEM);
    cudaFuncSetAttribute(mma_gemm<2>, cudaFuncAttributeMaxDynamicSharedMemorySize, MMA_SMEM);

    embed_pe_kernel<<<(Mm*(Ee/4) + 255)/256, 256>>>(h0h, h0l, embedW, x);
    conv2_kernel<<<(768*Ee/4 + 255)/256, 256>>>(w_ih_f, wfh, wfl, 768*Ee/4);
    mma_gemm<0><<<dim3(768/128, Mm/128), 256, MMA_SMEM>>>(
        h0h, h0l, wfh, wfl, b_ih_f, nullptr, gi0, nullptr, nullptr, Mm, 768, Ee);
    conv2_kernel<<<(768*Ee/4 + 255)/256, 256>>>(w_ih_b, wbh, wbl, 768*Ee/4);
    mma_gemm<0><<<dim3(768/128, Mm/128), 256, MMA_SMEM>>>(
        h0h, h0l, wbh, wbl, b_ih_b, nullptr, gi1, nullptr, nullptr, Mm, 768, Ee);

    zero_cnt_kernel<<<4, 256>>>(cnt);
    gru_persistent<<<384, 256, GRU_SMEM>>>(gi0, gi1, hcat, hch, hcl,
                                           w_hh_f, w_hh_b, b_hh_f, b_hh_b, cnt,
                                           ff_w1, ff_w2, w1h, w1l, w2h, w2l);

    for (int i = 0; i < 4; ++i) {
        size_t wo1 = (size_t)i*Dd*DFFv, wo2 = (size_t)i*DFFv*Dd;
        mma_gemm<1><<<dim3(DFFv/128, Mm/128), 256, MMA_SMEM>>>(
            hch, hcl, w1h + wo1, w1l + wo1, ff_b1 + (size_t)i*DFFv, nullptr,
            nullptr, mdh, mdl, Mm, DFFv, Dd);
        mma_gemm<2><<<dim3(Dd/128, Mm/128), 256, MMA_SMEM>>>(
            mdh, mdl, w2h + wo2, w2l + wo2, ff_b2 + (size_t)i*Dd, hcat,
            tmp, nullptr, nullptr, Mm, Dd, DFFv);
        ln_split2_kernel<<<Mm, 128>>>(tmp, hcat, hch, hcl,
                                      ln_g + (size_t)i*Dd, ln_b + (size_t)i*Dd);
    }

    fc_kernel<<<Mm/16, 256>>>(hcat, fc_w, fc_b, logit);
    viterbi_kernel<<<1, 512>>>(logit, y, trans, bp, out);
}

// round 13
// speedup vs baseline: 1.2045x; 1.0396x over previous
#include <cuda_runtime.h>
#include <cuda_fp16.h>
#include <cstdint>
#include <math.h>

#define Tt 512
#define Bb 32
#define Ee 512
#define Hh 256
#define Dd 512
#define DFFv 2048
#define Cc 16
#define Mm (Tt*Bb)

__device__ __forceinline__ uint32_t smem_u32(const void* p) {
    uint32_t a;
    asm("{ .reg .u64 t; cvta.to.shared.u64 t, %1; cvt.u32.u64 %0, t; }" : "=r"(a) : "l"(p));
    return a;
}
__device__ __forceinline__ void mma16816(float* c, const uint32_t* a, const uint32_t* b) {
    asm volatile("mma.sync.aligned.m16n8k16.row.col.f32.f16.f16.f32 "
        "{%0,%1,%2,%3}, {%4,%5,%6,%7}, {%8,%9}, {%0,%1,%2,%3};"
        : "+f"(c[0]), "+f"(c[1]), "+f"(c[2]), "+f"(c[3])
        : "r"(a[0]), "r"(a[1]), "r"(a[2]), "r"(a[3]), "r"(b[0]), "r"(b[1]));
}
__device__ __forceinline__ void ldsm4(uint32_t* r, uint32_t addr) {
    asm volatile("ldmatrix.sync.aligned.m8n8.x4.shared.b16 {%0,%1,%2,%3}, [%4];"
        : "=r"(r[0]), "=r"(r[1]), "=r"(r[2]), "=r"(r[3]) : "r"(addr));
}
__device__ __forceinline__ void ldsm2(uint32_t* r, uint32_t addr) {
    asm volatile("ldmatrix.sync.aligned.m8n8.x2.shared.b16 {%0,%1}, [%2];"
        : "=r"(r[0]), "=r"(r[1]) : "r"(addr));
}
#define CP_ASYNC16(dst, src) \
    asm volatile("cp.async.cg.shared.global [%0], [%1], 16;" :: "r"(dst), "l"(src))
#define CP_COMMIT() asm volatile("cp.async.commit_group;")
#define CP_WAIT(n)  asm volatile("cp.async.wait_group %0;" :: "n"(n) : "memory")

__device__ __forceinline__ void split2h(float v, __half& h, __half& l) {
    h = __float2half_rn(v);
    l = __float2half_rn(v - __half2float(h));
}
__device__ __forceinline__ void red_release(unsigned* p, unsigned v) {
    asm volatile("red.release.gpu.global.add.u32 [%0], %1;" :: "l"(p), "r"(v) : "memory");
}
__device__ __forceinline__ unsigned ld_acquire(const unsigned* p) {
    unsigned v;
    asm volatile("ld.acquire.gpu.global.u32 %0, [%1];" : "=r"(v) : "l"(p) : "memory");
    return v;
}

// ======== scratch carve-out ========
constexpr size_t AL64(size_t x) { return (x + 63) & ~(size_t)63; }
constexpr size_t SZ_PE = (size_t)Tt*Ee;
constexpr size_t SZ_GI = (size_t)Mm*3*Hh, SZ_HC = (size_t)Mm*Dd;
constexpr size_t SZ_LOG = (size_t)Mm*Cc, SZ_BPF = AL64(((size_t)(Tt-1)*Bb*Cc + 3)/4);
constexpr size_t SZ_H0S = (size_t)Mm*Ee/2, SZ_HCS = (size_t)Mm*Dd/2, SZ_MDS = (size_t)Mm*DFFv/2;
constexpr size_t SZ_W1S = (size_t)4*Dd*DFFv/2, SZ_W2S = (size_t)4*DFFv*Dd/2, SZ_WIS = (size_t)3*Hh*Ee/2;
constexpr size_t OFF_PE  = 0;
constexpr size_t OFF_GI0 = AL64(OFF_PE + SZ_PE);
constexpr size_t OFF_GI1 = AL64(OFF_GI0 + SZ_GI);
constexpr size_t OFF_HCAT= AL64(OFF_GI1 + SZ_GI);
constexpr size_t OFF_TMP = AL64(OFF_HCAT + SZ_HC);
constexpr size_t OFF_LOG = AL64(OFF_TMP + SZ_HC);
constexpr size_t OFF_BP  = AL64(OFF_LOG + SZ_LOG);
constexpr size_t OFF_CNT = AL64(OFF_BP + SZ_BPF);
constexpr size_t OFF_H0H = AL64(OFF_CNT + 1024);
constexpr size_t OFF_H0L = AL64(OFF_H0H + SZ_H0S);
constexpr size_t OFF_HCH = AL64(OFF_H0L + SZ_H0S);
constexpr size_t OFF_HCL = AL64(OFF_HCH + SZ_HCS);
constexpr size_t OFF_MDH = AL64(OFF_HCL + SZ_HCS);
constexpr size_t OFF_MDL = AL64(OFF_MDH + SZ_MDS);
constexpr size_t OFF_W1H = AL64(OFF_MDL + SZ_MDS);
constexpr size_t OFF_W1L = AL64(OFF_W1H + SZ_W1S);
constexpr size_t OFF_W2H = AL64(OFF_W1L + SZ_W1S);
constexpr size_t OFF_W2L = AL64(OFF_W2H + SZ_W2S);
constexpr size_t OFF_WFH = AL64(OFF_W2L + SZ_W2S);
constexpr size_t OFF_WFL = AL64(OFF_WFH + SZ_WIS);
constexpr size_t OFF_WBH = AL64(OFF_WFL + SZ_WIS);
constexpr size_t OFF_WBL = AL64(OFF_WBH + SZ_WIS);
constexpr size_t TOTAL_F = AL64(OFF_WBL + SZ_WIS);

__device__ __align__(256) float g_buf[TOTAL_F];

// ======== positional encoding table (one-time, 262K elements) ========
__global__ void pe_kernel(float* __restrict__ pe) {
    int idx = blockIdx.x * blockDim.x + threadIdx.x;
    if (idx >= Tt*Ee) return;
    int t = idx >> 9, e = idx & 511, i2 = e & ~1;
    double div = exp(-log(10000.0) * (double)i2 / (double)Ee);
    double a = (double)t * div;
    pe[idx] = (float)((e & 1) ? cos(a) : sin(a));
}

// ======== embedding + pe table -> 2-limb fp16 (memory-bound, fp32) ========
__global__ __launch_bounds__(256)
void embed2_kernel(__half* __restrict__ oh, __half* __restrict__ ol,
                   const float* __restrict__ emb, const int* __restrict__ x,
                   const float* __restrict__ pe) {
    int idx = blockIdx.x * blockDim.x + threadIdx.x;
    if (idx >= Mm * (Ee/4)) return;
    int row = idx >> 7, e4 = idx & 127;
    int t = row >> 5, b = row & 31;
    int tok = x[(size_t)b*Tt + t];
    float4 ev = *(const float4*)(emb + (size_t)tok*Ee + e4*4);
    float4 pv = *(const float4*)(pe  + (size_t)t*Ee  + e4*4);
    float v[4] = {ev.x+pv.x, ev.y+pv.y, ev.z+pv.z, ev.w+pv.w};
    size_t o = (size_t)row*Ee + e4*4;
    #pragma unroll
    for (int q = 0; q < 4; ++q) { __half h, l; split2h(v[q], h, l); oh[o+q] = h; ol[o+q] = l; }
}

// ======== elementwise fp32 -> 2 limbs ========
__global__ void conv2_kernel(const float* __restrict__ in, __half* __restrict__ oh,
                             __half* __restrict__ ol, int n4) {
    int idx = blockIdx.x * blockDim.x + threadIdx.x;
    if (idx >= n4) return;
    float4 v4 = *(const float4*)(in + (size_t)idx*4);
    float v[4] = {v4.x, v4.y, v4.z, v4.w};
    size_t o = (size_t)idx*4;
    #pragma unroll
    for (int q = 0; q < 4; ++q) { __half h, l; split2h(v[q], h, l); oh[o+q] = h; ol[o+q] = l; }
}

// ======== fp16 2-limb MMA GEMM (proven config) ========
#define LDSH 40
#define TILE_H (128*LDSH)
#define STAGE_H (4*TILE_H)
#define MMA_SMEM (2*STAGE_H*2)

template<int EPI>
__global__ __launch_bounds__(256)
void mma_gemm(const __half* __restrict__ Ah, const __half* __restrict__ Al,
              const __half* __restrict__ Bh, const __half* __restrict__ Bl,
              const float* __restrict__ bias, const float* __restrict__ res,
              float* __restrict__ Cf, __half* __restrict__ Ch, __half* __restrict__ Cl,
              int M, int N, int K) {
    extern __shared__ __half sh[];
    int tid = threadIdx.x, lane = tid & 31, wid = tid >> 5;
    int m0 = blockIdx.y * 128, n0 = blockIdx.x * 128;
    int wrow = wid & 1, wcol = wid >> 1;
    const __half* gp[4] = {Ah + (size_t)m0*K, Al + (size_t)m0*K,
                           Bh + (size_t)n0*K, Bl + (size_t)n0*K};
    uint32_t sbase = smem_u32(sh);
    int NC = K >> 5;

    float acc[4][4][4];
    #pragma unroll
    for (int a = 0; a < 4; ++a)
        #pragma unroll
        for (int b = 0; b < 4; ++b)
            #pragma unroll
            for (int q = 0; q < 4; ++q) acc[a][b][q] = 0.f;

    {
        #pragma unroll
        for (int i = 0; i < 8; ++i) {
            int idx = tid + i*256;
            int arr = idx >> 9, r = (idx >> 2) & 127, v = idx & 3;
            uint32_t dst = sbase + (uint32_t)(arr*TILE_H + r*LDSH + v*8)*2;
            CP_ASYNC16(dst, gp[arr] + (size_t)r*K + v*8);
        }
        CP_COMMIT();
    }
    for (int c = 0; c < NC; ++c) {
        if (c + 1 < NC) {
            int s = (c+1) & 1;
            #pragma unroll
            for (int i = 0; i < 8; ++i) {
                int idx = tid + i*256;
                int arr = idx >> 9, r = (idx >> 2) & 127, v = idx & 3;
                uint32_t dst = sbase + (uint32_t)(s*STAGE_H + arr*TILE_H + r*LDSH + v*8)*2;
                CP_ASYNC16(dst, gp[arr] + (size_t)r*K + (c+1)*32 + v*8);
            }
            CP_COMMIT();
            CP_WAIT(1);
        } else {
            CP_WAIT(0);
        }
        __syncthreads();
        uint32_t stg = sbase + (uint32_t)((c & 1)*STAGE_H)*2;
        #pragma unroll
        for (int kh2 = 0; kh2 < 2; ++kh2) {
            int ks = kh2*16;
            uint32_t ah[4][4], al[4][4], bh[4][2], bl[4][2];
            #pragma unroll
            for (int mt = 0; mt < 4; ++mt) {
                int row = wrow*64 + mt*16 + (lane & 15);
                uint32_t off = (uint32_t)(row*LDSH + ks + (lane >> 4)*8)*2;
                ldsm4(ah[mt], stg + off);
                ldsm4(al[mt], stg + (uint32_t)TILE_H*2 + off);
            }
            #pragma unroll
            for (int nt = 0; nt < 4; ++nt) {
                int l4 = lane & 15;
                int nr = wcol*32 + nt*8 + (l4 & 7);
                uint32_t off = (uint32_t)(nr*LDSH + ks + (l4 >> 3)*8)*2;
                ldsm2(bh[nt], stg + (uint32_t)(2*TILE_H)*2 + off);
                ldsm2(bl[nt], stg + (uint32_t)(3*TILE_H)*2 + off);
            }
            #pragma unroll
            for (int mt = 0; mt < 4; ++mt)
                #pragma unroll
                for (int nt = 0; nt < 4; ++nt)
                    mma16816(acc[mt][nt], ah[mt], bh[nt]);
            #pragma unroll
            for (int mt = 0; mt < 4; ++mt)
                #pragma unroll
                for (int nt = 0; nt < 4; ++nt)
                    mma16816(acc[mt][nt], ah[mt], bl[nt]);
            #pragma unroll
            for (int mt = 0; mt < 4; ++mt)
                #pragma unroll
                for (int nt = 0; nt < 4; ++nt)
                    mma16816(acc[mt][nt], al[mt], bh[nt]);
        }
        __syncthreads();
    }

    int group = lane >> 2, tig = lane & 3;
    #pragma unroll
    for (int mt = 0; mt < 4; ++mt)
        #pragma unroll
        for (int nt = 0; nt < 4; ++nt) {
            int r = m0 + wrow*64 + mt*16 + group;
            int cc = n0 + wcol*32 + nt*8 + tig*2;
            float b0 = bias[cc], b1 = bias[cc+1];
            #pragma unroll
            for (int half = 0; half < 2; ++half) {
                int rr = r + half*8;
                float v0 = acc[mt][nt][half*2+0] + b0;
                float v1 = acc[mt][nt][half*2+1] + b1;
                if (EPI == 1) {
                    v0 = fmaxf(v0, 0.f); v1 = fmaxf(v1, 0.f);
                    __half h0, l0, h1, l1;
                    split2h(v0, h0, l0); split2h(v1, h1, l1);
                    *(__half2*)(Ch + (size_t)rr*N + cc) = __halves2half2(h0, h1);
                    *(__half2*)(Cl + (size_t)rr*N + cc) = __halves2half2(l0, l1);
                } else {
                    if (EPI == 2) {
                        float2 r2 = *(const float2*)(res + (size_t)rr*N + cc);
                        v0 += r2.x; v1 += r2.y;
                    }
                    float2 o; o.x = v0; o.y = v1;
                    *(float2*)(Cf + (size_t)rr*N + cc) = o;
                }
            }
        }
}

// ======== counter zeroing ========
__global__ void zero_cnt_kernel(unsigned* __restrict__ c) {
    c[blockIdx.x * blockDim.x + threadIdx.x] = 0u;
}

// ======== persistent GRU v4 (R11/R12 proven) + concurrent FF conversion ========
#define GRU_SMEM ((6*272 + 32*272) * 4)
__global__ __launch_bounds__(256)
void gru_persistent(const float* __restrict__ gi0, const float* __restrict__ gi1,
                    float* __restrict__ hcat,
                    __half* __restrict__ hch, __half* __restrict__ hcl,
                    const float* __restrict__ whhF, const float* __restrict__ whhB,
                    const float* __restrict__ bhhF, const float* __restrict__ bhhB,
                    unsigned* __restrict__ cnt,
                    const float* __restrict__ ff_w1, const float* __restrict__ ff_w2,
                    __half* __restrict__ w1h, __half* __restrict__ w1l,
                    __half* __restrict__ w2h, __half* __restrict__ w2l) {
    extern __shared__ float sm[];
    int tid = threadIdx.x;

    if (blockIdx.x >= 256) {
        float* tsm = sm;
        int tx = tid & 31, ty8 = tid >> 5;
        int cid = blockIdx.x - 256;
        for (int tile = cid; tile < 8192; tile += 128) {
            int blk = tile >> 11, rem = tile & 2047;
            const float* in; __half *oh, *ol; int R, C, t2;
            if (rem < 1024) {
                size_t wo = (size_t)blk*Dd*DFFv;
                in = ff_w1 + wo; oh = w1h + wo; ol = w1l + wo;
                R = Dd; C = DFFv; t2 = rem;
            } else {
                size_t wo = (size_t)blk*DFFv*Dd;
                in = ff_w2 + wo; oh = w2h + wo; ol = w2l + wo;
                R = DFFv; C = Dd; t2 = rem - 1024;
            }
            int ntx = C >> 5;
            int c0 = (t2 % ntx) << 5, r0 = (t2 / ntx) << 5;
            #pragma unroll
            for (int i = 0; i < 32; i += 8)
                tsm[(ty8 + i)*33 + tx] = in[(size_t)(r0 + ty8 + i)*C + c0 + tx];
            __syncthreads();
            #pragma unroll
            for (int i = 0; i < 32; i += 8) {
                __half h, l;
                split2h(tsm[tx*33 + ty8 + i], h, l);
                size_t o = (size_t)(c0 + ty8 + i)*R + r0 + tx;
                oh[o] = h; ol[o] = l;
            }
            __syncthreads();
        }
        return;
    }

    float* w_s = sm;
    float* h_s = sm + 6*272;
    int dir = blockIdx.x >> 7, cta = blockIdx.x & 127;
    const float* gi  = dir ? gi1  : gi0;
    const float* whh = dir ? whhB : whhF;
    const float* bhh = dir ? bhhB : bhhF;
    unsigned* mycnt = cnt + dir * Tt;
    int jbase = cta * 2;

    for (int i = tid; i < 6*64; i += 256) {
        int lr = i >> 6, k4 = i & 63;
        int jl = lr / 3, g = lr % 3;
        float4 wv = *(const float4*)(whh + (size_t)(g*Hh + jbase + jl)*Hh + k4*4);
        *(float4*)&w_s[lr*272 + (k4 >> 4)*68 + (k4 & 15)*4] = wv;
    }
    int lane = tid & 31, w = tid >> 5;
    int kh = lane & 3;
    int b  = ((w & 3) << 3) | (lane >> 2);
    int jl = w >> 2;
    int j = jbase + jl;
    float brr = bhh[j], bz = bhh[256 + j], bn_ = bhh[512 + j];
    const float* wr = w_s + (jl*3 + 0)*272 + kh*68;
    const float* wz = w_s + (jl*3 + 1)*272 + kh*68;
    const float* wn = w_s + (jl*3 + 2)*272 + kh*68;
    __syncthreads();

    for (int s = 0; s < Tt; ++s) {
        int t = dir ? (Tt - 1 - s) : s;
        const float* gib = gi + (size_t)t*Bb*768 + (size_t)b*768;
        float g_r = gib[j], g_z = gib[256 + j], g_n = gib[512 + j];
        const float* hp = nullptr;
        if (s > 0)
            hp = dir ? (hcat + (size_t)(t+1)*Bb*Dd + Hh) : (hcat + (size_t)(t-1)*Bb*Dd);
        if (hp) {
            for (int i = tid; i < 32*64; i += 256) {
                int bb = i >> 6, k4 = i & 63;
                float4 hv = *(const float4*)(hp + (size_t)bb*Dd + k4*4);
                *(float4*)&h_s[bb*272 + (k4 >> 4)*68 + (k4 & 15)*4] = hv;
            }
        } else {
            for (int i = tid; i < 32*272; i += 256) h_s[i] = 0.f;
        }
        __syncthreads();

        const float* hb = h_s + b*272 + kh*68;
        float ar = 0.f, az = 0.f, an = 0.f;
        #pragma unroll
        for (int k4 = 0; k4 < 16; ++k4) {
            float4 h4  = *(const float4*)(hb + k4*4);
            float4 w_r = *(const float4*)(wr + k4*4);
            float4 w_z = *(const float4*)(wz + k4*4);
            float4 w_n = *(const float4*)(wn + k4*4);
            ar += w_r.x*h4.x + w_r.y*h4.y + w_r.z*h4.z + w_r.w*h4.w;
            az += w_z.x*h4.x + w_z.y*h4.y + w_z.z*h4.z + w_z.w*h4.w;
            an += w_n.x*h4.x + w_n.y*h4.y + w_n.z*h4.z + w_n.w*h4.w;
        }
        ar += __shfl_xor_sync(0xffffffffu, ar, 1);
        az += __shfl_xor_sync(0xffffffffu, az, 1);
        an += __shfl_xor_sync(0xffffffffu, an, 1);
        ar += __shfl_xor_sync(0xffffffffu, ar, 2);
        az += __shfl_xor_sync(0xffffffffu, az, 2);
        an += __shfl_xor_sync(0xffffffffu, an, 2);

        if (kh == 0) {
            float hprev_v = h_s[b*272 + (j >> 6)*68 + (j & 63)];
            float r = 1.f / (1.f + expf(-(g_r + ar + brr)));
            float z = 1.f / (1.f + expf(-(g_z + az + bz)));
            float n = tanhf(g_n + r*(an + bn_));
            float hv = (1.f - z)*n + z*hprev_v;
            size_t oo = (size_t)t*Bb*Dd + (size_t)b*Dd + dir*Hh + j;
            hcat[oo] = hv;
            __half hh, hl;
            split2h(hv, hh, hl);
            hch[oo] = hh; hcl[oo] = hl;
        }

        __syncthreads();
        if (tid == 0) {
            red_release(mycnt + s, 1u);
            while (ld_acquire(mycnt + s) < 128u) { }
        }
        __syncthreads();
    }
}

// ======== LayerNorm + optional fused 2-limb split ========
__global__ __launch_bounds__(128)
void ln_split2_kernel(const float* __restrict__ in, float* __restrict__ out,
                      __half* __restrict__ oh, __half* __restrict__ ol,
                      const float* __restrict__ g, const float* __restrict__ bta) {
    int row = blockIdx.x, tid = threadIdx.x;
    __shared__ float red[4];
    float4 v = *(const float4*)(in + (size_t)row*Dd + tid*4);
    float s = v.x + v.y + v.z + v.w;
    #pragma unroll
    for (int o = 16; o; o >>= 1) s += __shfl_xor_sync(0xffffffffu, s, o);
    if ((tid & 31) == 0) red[tid >> 5] = s;
    __syncthreads();
    float mean = (red[0]+red[1]+red[2]+red[3]) * (1.f/512.f);
    float dx = v.x-mean, dy = v.y-mean, dz = v.z-mean, dw = v.w-mean;
    float q = dx*dx + dy*dy + dz*dz + dw*dw;
    #pragma unroll
    for (int o = 16; o; o >>= 1) q += __shfl_xor_sync(0xffffffffu, q, o);
    __syncthreads();
    if ((tid & 31) == 0) red[tid >> 5] = q;
    __syncthreads();
    float var = (red[0]+red[1]+red[2]+red[3]) * (1.f/512.f);
    float rs = rsqrtf(var + 1e-5f);
    float4 g4 = *(const float4*)(g   + tid*4);
    float4 b4 = *(const float4*)(bta + tid*4);
    float ov[4];
    ov[0] = dx*rs*g4.x + b4.x; ov[1] = dy*rs*g4.y + b4.y;
    ov[2] = dz*rs*g4.z + b4.z; ov[3] = dw*rs*g4.w + b4.w;
    *(float4*)(out + (size_t)row*Dd + tid*4) = *(float4*)ov;
    if (oh) {
        size_t o = (size_t)row*Dd + tid*4;
        #pragma unroll
        for (int qq = 0; qq < 4; ++qq) {
            __half h, l;
            split2h(ov[qq], h, l);
            oh[o+qq] = h; ol[o+qq] = l;
        }
    }
}

// ======== FC ========
__global__ __launch_bounds__(256)
void fc_kernel(const float* __restrict__ A, const float* __restrict__ W,
               const float* __restrict__ bias, float* __restrict__ out) {
    __shared__ float Ws[Dd*Cc];
    int tid = threadIdx.x;
    for (int i = tid; i < Dd*Cc; i += 256) Ws[i] = W[i];
    __syncthreads();
    int r = tid >> 4, c = tid & 15;
    size_t row = (size_t)blockIdx.x*16 + r;
    const float* a = A + row*Dd;
    float acc = bias[c];
    #pragma unroll 4
    for (int k4 = 0; k4 < Dd/4; ++k4) {
        float4 av = *(const float4*)(a + k4*4);
        int kb = k4*4;
        acc += av.x*Ws[(kb+0)*Cc + c] + av.y*Ws[(kb+1)*Cc + c]
             + av.z*Ws[(kb+2)*Cc + c] + av.w*Ws[(kb+3)*Cc + c];
    }
    out[row*Cc + c] = acc;
}

// ======== Viterbi: warp-shuffle scores, no block barriers in main loop ========
__global__ __launch_bounds__(512)
void viterbi_kernel(const float* __restrict__ logits, const int* __restrict__ y,
                    const float* __restrict__ trans, unsigned char* __restrict__ bp,
                    float* __restrict__ out) {
    __shared__ unsigned char path[32][512];
    __shared__ int tag_s[32];
    __shared__ unsigned ymask[32][16];
    int tid = threadIdx.x;
    int lane = tid & 31;
    int sub = lane >> 4, c = lane & 15;
    int b = ((tid >> 5) << 1) | sub;

    // build y!=PAD bitmasks (32 batches x 512 bits)
    for (int i = tid; i < 32*16; i += 512) {
        int bb = i >> 4, w32 = i & 15;
        unsigned m = 0;
        #pragma unroll 8
        for (int k = 0; k < 32; ++k)
            if (y[(size_t)bb*Tt + w32*32 + k] != 0) m |= (1u << k);
        ymask[bb][w32] = m;
    }
    float trp[16];
    #pragma unroll
    for (int pv = 0; pv < 16; ++pv) trp[pv] = trans[pv*16 + c];
    __syncthreads();

    float score = trans[16 + c] + logits[(size_t)b*16 + c];   // trans[BOS] + emit[0]
    int half = lane & 16;
    for (int t = 1; t < Tt; ++t) {
        float e = logits[(size_t)t*512 + tid];
        float best = -1e30f; int arg = 0;
        #pragma unroll
        for (int pv = 0; pv < 16; ++pv) {
            float sv = __shfl_sync(0xffffffffu, score, half | pv);
            float v = sv + trp[pv];
            if (v > best) { best = v; arg = pv; }
        }
        bool m = (ymask[b][t >> 5] >> (t & 31)) & 1u;
        bp[(size_t)(t-1)*512 + tid] = (unsigned char)arg;
        score = m ? (best + e) : score;
    }
    float fin = score + trans[c*16 + 2];                      // + trans[:,EOS]
    float best = -1e30f; int arg = 0;
    #pragma unroll
    for (int k = 0; k < 16; ++k) {
        float v = __shfl_sync(0xffffffffu, fin, half | k);
        if (v > best) { best = v; arg = k; }
    }
    if (c == 0) { out[b] = best; tag_s[b] = arg; }
    __syncthreads();
    if (tid < 32) {
        int bb = tid;
        int tag = tag_s[bb];
        for (int i = Tt - 2; i >= 0; --i) {
            path[bb][i+1] = (unsigned char)tag;
            if ((ymask[bb][(i+1) >> 5] >> ((i+1) & 31)) & 1u)
                tag = bp[(size_t)i*512 + bb*16 + tag];
        }
        path[bb][0] = (unsigned char)tag;
    }
    __syncthreads();
    for (int i = tid; i < 32*512; i += 512)
        out[32 + i] = (float)path[i >> 9][i & 511];
}

// ======== launcher ========
extern "C" void kernel_launch(void* const* d_in, const int* in_sizes, int n_in,
                              void* d_out, int out_size) {
    const int*   x      = (const int*)d_in[0];
    const int*   y      = (const int*)d_in[1];
    const float* embedW = (const float*)d_in[2];
    const float* w_ih_f = (const float*)d_in[3];
    const float* w_hh_f = (const float*)d_in[4];
    const float* b_ih_f = (const float*)d_in[5];
    const float* b_hh_f = (const float*)d_in[6];
    const float* w_ih_b = (const float*)d_in[7];
    const float* w_hh_b = (const float*)d_in[8];
    const float* b_ih_b = (const float*)d_in[9];
    const float* b_hh_b = (const float*)d_in[10];
    const float* ff_w1  = (const float*)d_in[11];
    const float* ff_b1  = (const float*)d_in[12];
    const float* ff_w2  = (const float*)d_in[13];
    const float* ff_b2  = (const float*)d_in[14];
    const float* ln_g   = (const float*)d_in[15];
    const float* ln_b   = (const float*)d_in[16];
    const float* fc_w   = (const float*)d_in[17];
    const float* fc_b   = (const float*)d_in[18];
    const float* trans  = (const float*)d_in[19];
    float* out = (float*)d_out;

    float* buf = nullptr;
    cudaGetSymbolAddress((void**)&buf, g_buf);
    float* pe    = buf + OFF_PE;
    float* gi0   = buf + OFF_GI0;
    float* gi1   = buf + OFF_GI1;
    float* hcat  = buf + OFF_HCAT;
    float* tmp   = buf + OFF_TMP;
    float* logit = buf + OFF_LOG;
    unsigned char* bp = (unsigned char*)(buf + OFF_BP);
    unsigned* cnt = (unsigned*)(buf + OFF_CNT);
    __half* h0h = (__half*)(buf + OFF_H0H);
    __half* h0l = (__half*)(buf + OFF_H0L);
    __half* hch = (__half*)(buf + OFF_HCH);
    __half* hcl = (__half*)(buf + OFF_HCL);
    __half* mdh = (__half*)(buf + OFF_MDH);
    __half* mdl = (__half*)(buf + OFF_MDL);
    __half* w1h = (__half*)(buf + OFF_W1H);
    __half* w1l = (__half*)(buf + OFF_W1L);
    __half* w2h = (__half*)(buf + OFF_W2H);
    __half* w2l = (__half*)(buf + OFF_W2L);
    __half* wfh = (__half*)(buf + OFF_WFH);
    __half* wfl = (__half*)(buf + OFF_WFL);
    __half* wbh = (__half*)(buf + OFF_WBH);
    __half* wbl = (__half*)(buf + OFF_WBL);

    cudaFuncSetAttribute(gru_persistent, cudaFuncAttributeMaxDynamicSharedMemorySize, GRU_SMEM);
    cudaFuncSetAttribute(mma_gemm<0>, cudaFuncAttributeMaxDynamicSharedMemorySize, MMA_SMEM);
    cudaFuncSetAttribute(mma_gemm<1>, cudaFuncAttributeMaxDynamicSharedMemorySize, MMA_SMEM);
    cudaFuncSetAttribute(mma_gemm<2>, cudaFuncAttributeMaxDynamicSharedMemorySize, MMA_SMEM);

    pe_kernel<<<(Tt*Ee + 255)/256, 256>>>(pe);
    embed2_kernel<<<(Mm*(Ee/4) + 255)/256, 256>>>(h0h, h0l, embedW, x, pe);
    conv2_kernel<<<(768*Ee/4 + 255)/256, 256>>>(w_ih_f, wfh, wfl, 768*Ee/4);
    mma_gemm<0><<<dim3(768/128, Mm/128), 256, MMA_SMEM>>>(
        h0h, h0l, wfh, wfl, b_ih_f, nullptr, gi0, nullptr, nullptr, Mm, 768, Ee);
    conv2_kernel<<<(768*Ee/4 + 255)/256, 256>>>(w_ih_b, wbh, wbl, 768*Ee/4);
    mma_gemm<0><<<dim3(768/128, Mm/128), 256, MMA_SMEM>>>(
        h0h, h0l, wbh, wbl, b_ih_b, nullptr, gi1, nullptr, nullptr, Mm, 768, Ee);

    zero_cnt_kernel<<<4, 256>>>(cnt);
    gru_persistent<<<384, 256, GRU_SMEM>>>(gi0, gi1, hcat, hch, hcl,
                                           w_hh_f, w_hh_b, b_hh_f, b_hh_b, cnt,
                                           ff_w1, ff_w2, w1h, w1l, w2h, w2l);

    for (int i = 0; i < 4; ++i) {
        size_t wo1 = (size_t)i*Dd*DFFv, wo2 = (size_t)i*DFFv*Dd;
        mma_gemm<1><<<dim3(DFFv/128, Mm/128), 256, MMA_SMEM>>>(
            hch, hcl, w1h + wo1, w1l + wo1, ff_b1 + (size_t)i*DFFv, nullptr,
            nullptr, mdh, mdl, Mm, DFFv, Dd);
        mma_gemm<2><<<dim3(Dd/128, Mm/128), 256, MMA_SMEM>>>(
            mdh, mdl, w2h + wo2, w2l + wo2, ff_b2 + (size_t)i*Dd, hcat,
            tmp, nullptr, nullptr, Mm, Dd, DFFv);
        bool last = (i == 3);
        ln_split2_kernel<<<Mm, 128>>>(tmp, hcat,
                                      last ? nullptr : hch, last ? nullptr : hcl,
                                      ln_g + (size_t)i*Dd, ln_b + (size_t)i*Dd);
    }

    fc_kernel<<<Mm/16, 256>>>(hcat, fc_w, fc_b, logit);
    viterbi_kernel<<<1, 512>>>(logit, y, trans, bp, out);
}

// round 14
// speedup vs baseline: 1.3556x; 1.1254x over previous
#include <cuda_runtime.h>
#include <cuda_fp16.h>
#include <cstdint>
#include <math.h>

#define Tt 512
#define Bb 32
#define Ee 512
#define Hh 256
#define Dd 512
#define DFFv 2048
#define Cc 16
#define Mm (Tt*Bb)

__device__ __forceinline__ uint32_t smem_u32(const void* p) {
    uint32_t a;
    asm("{ .reg .u64 t; cvta.to.shared.u64 t, %1; cvt.u32.u64 %0, t; }" : "=r"(a) : "l"(p));
    return a;
}
__device__ __forceinline__ void mma16816(float* c, const uint32_t* a, const uint32_t* b) {
    asm volatile("mma.sync.aligned.m16n8k16.row.col.f32.f16.f16.f32 "
        "{%0,%1,%2,%3}, {%4,%5,%6,%7}, {%8,%9}, {%0,%1,%2,%3};"
        : "+f"(c[0]), "+f"(c[1]), "+f"(c[2]), "+f"(c[3])
        : "r"(a[0]), "r"(a[1]), "r"(a[2]), "r"(a[3]), "r"(b[0]), "r"(b[1]));
}
__device__ __forceinline__ void ldsm4(uint32_t* r, uint32_t addr) {
    asm volatile("ldmatrix.sync.aligned.m8n8.x4.shared.b16 {%0,%1,%2,%3}, [%4];"
        : "=r"(r[0]), "=r"(r[1]), "=r"(r[2]), "=r"(r[3]) : "r"(addr));
}
__device__ __forceinline__ void ldsm2(uint32_t* r, uint32_t addr) {
    asm volatile("ldmatrix.sync.aligned.m8n8.x2.shared.b16 {%0,%1}, [%2];"
        : "=r"(r[0]), "=r"(r[1]) : "r"(addr));
}
#define CP_ASYNC16(dst, src) \
    asm volatile("cp.async.cg.shared.global [%0], [%1], 16;" :: "r"(dst), "l"(src))
#define CP_COMMIT() asm volatile("cp.async.commit_group;")
#define CP_WAIT(n)  asm volatile("cp.async.wait_group %0;" :: "n"(n) : "memory")

__device__ __forceinline__ void split2h(float v, __half& h, __half& l) {
    h = __float2half_rn(v);
    l = __float2half_rn(v - __half2float(h));
}
__device__ __forceinline__ void red_release(unsigned* p, unsigned v) {
    asm volatile("red.release.gpu.global.add.u32 [%0], %1;" :: "l"(p), "r"(v) : "memory");
}
__device__ __forceinline__ unsigned ld_acquire(const unsigned* p) {
    unsigned v;
    asm volatile("ld.acquire.gpu.global.u32 %0, [%1];" : "=r"(v) : "l"(p) : "memory");
    return v;
}

// ======== scratch carve-out ========
constexpr size_t AL64(size_t x) { return (x + 63) & ~(size_t)63; }
constexpr size_t SZ_PE = (size_t)Tt*Ee;
constexpr size_t SZ_GI = (size_t)Mm*3*Hh, SZ_HC = (size_t)Mm*Dd;
constexpr size_t SZ_LOG = (size_t)Mm*Cc, SZ_BPF = AL64(((size_t)(Tt-1)*Bb*Cc + 3)/4);
constexpr size_t SZ_H0S = (size_t)Mm*Ee/2, SZ_HCS = (size_t)Mm*Dd/2, SZ_MDS = (size_t)Mm*DFFv/2;
constexpr size_t SZ_W1S = (size_t)4*Dd*DFFv/2, SZ_W2S = (size_t)4*DFFv*Dd/2, SZ_WIS = (size_t)3*Hh*Ee/2;
constexpr size_t OFF_PE  = 0;
constexpr size_t OFF_GI0 = AL64(OFF_PE + SZ_PE);
constexpr size_t OFF_GI1 = AL64(OFF_GI0 + SZ_GI);
constexpr size_t OFF_HCAT= AL64(OFF_GI1 + SZ_GI);
constexpr size_t OFF_TMP = AL64(OFF_HCAT + SZ_HC);
constexpr size_t OFF_LOG = AL64(OFF_TMP + SZ_HC);
constexpr size_t OFF_BP  = AL64(OFF_LOG + SZ_LOG);
constexpr size_t OFF_CNT = AL64(OFF_BP + SZ_BPF);          // 4096 u32 (2 dir x 4 grp x 512)
constexpr size_t OFF_H0H = AL64(OFF_CNT + 4096);
constexpr size_t OFF_H0L = AL64(OFF_H0H + SZ_H0S);
constexpr size_t OFF_HCH = AL64(OFF_H0L + SZ_H0S);
constexpr size_t OFF_HCL = AL64(OFF_HCH + SZ_HCS);
constexpr size_t OFF_MDH = AL64(OFF_HCL + SZ_HCS);
constexpr size_t OFF_MDL = AL64(OFF_MDH + SZ_MDS);
constexpr size_t OFF_W1H = AL64(OFF_MDL + SZ_MDS);
constexpr size_t OFF_W1L = AL64(OFF_W1H + SZ_W1S);
constexpr size_t OFF_W2H = AL64(OFF_W1L + SZ_W1S);
constexpr size_t OFF_W2L = AL64(OFF_W2H + SZ_W2S);
constexpr size_t OFF_WFH = AL64(OFF_W2L + SZ_W2S);
constexpr size_t OFF_WFL = AL64(OFF_WFH + SZ_WIS);
constexpr size_t OFF_WBH = AL64(OFF_WFL + SZ_WIS);
constexpr size_t OFF_WBL = AL64(OFF_WBH + SZ_WIS);
constexpr size_t TOTAL_F = AL64(OFF_WBL + SZ_WIS);

__device__ __align__(256) float g_buf[TOTAL_F];

// ======== positional encoding table ========
__global__ void pe_kernel(float* __restrict__ pe) {
    int idx = blockIdx.x * blockDim.x + threadIdx.x;
    if (idx >= Tt*Ee) return;
    int t = idx >> 9, e = idx & 511, i2 = e & ~1;
    double div = exp(-log(10000.0) * (double)i2 / (double)Ee);
    double a = (double)t * div;
    pe[idx] = (float)((e & 1) ? cos(a) : sin(a));
}

// ======== embedding + pe -> 2-limb fp16 ========
__global__ __launch_bounds__(256)
void embed2_kernel(__half* __restrict__ oh, __half* __restrict__ ol,
                   const float* __restrict__ emb, const int* __restrict__ x,
                   const float* __restrict__ pe) {
    int idx = blockIdx.x * blockDim.x + threadIdx.x;
    if (idx >= Mm * (Ee/4)) return;
    int row = idx >> 7, e4 = idx & 127;
    int t = row >> 5, b = row & 31;
    int tok = x[(size_t)b*Tt + t];
    float4 ev = *(const float4*)(emb + (size_t)tok*Ee + e4*4);
    float4 pv = *(const float4*)(pe  + (size_t)t*Ee  + e4*4);
    float v[4] = {ev.x+pv.x, ev.y+pv.y, ev.z+pv.z, ev.w+pv.w};
    size_t o = (size_t)row*Ee + e4*4;
    #pragma unroll
    for (int q = 0; q < 4; ++q) { __half h, l; split2h(v[q], h, l); oh[o+q] = h; ol[o+q] = l; }
}

// ======== elementwise fp32 -> 2 limbs ========
__global__ void conv2_kernel(const float* __restrict__ in, __half* __restrict__ oh,
                             __half* __restrict__ ol, int n4) {
    int idx = blockIdx.x * blockDim.x + threadIdx.x;
    if (idx >= n4) return;
    float4 v4 = *(const float4*)(in + (size_t)idx*4);
    float v[4] = {v4.x, v4.y, v4.z, v4.w};
    size_t o = (size_t)idx*4;
    #pragma unroll
    for (int q = 0; q < 4; ++q) { __half h, l; split2h(v[q], h, l); oh[o+q] = h; ol[o+q] = l; }
}

// ======== fp16 2-limb MMA GEMM (at mma.sync floor; unchanged) ========
#define LDSH 40
#define TILE_H (128*LDSH)
#define STAGE_H (4*TILE_H)
#define MMA_SMEM (2*STAGE_H*2)

template<int EPI>
__global__ __launch_bounds__(256)
void mma_gemm(const __half* __restrict__ Ah, const __half* __restrict__ Al,
              const __half* __restrict__ Bh, const __half* __restrict__ Bl,
              const float* __restrict__ bias, const float* __restrict__ res,
              float* __restrict__ Cf, __half* __restrict__ Ch, __half* __restrict__ Cl,
              int M, int N, int K) {
    extern __shared__ __half sh[];
    int tid = threadIdx.x, lane = tid & 31, wid = tid >> 5;
    int m0 = blockIdx.y * 128, n0 = blockIdx.x * 128;
    int wrow = wid & 1, wcol = wid >> 1;
    const __half* gp[4] = {Ah + (size_t)m0*K, Al + (size_t)m0*K,
                           Bh + (size_t)n0*K, Bl + (size_t)n0*K};
    uint32_t sbase = smem_u32(sh);
    int NC = K >> 5;

    float acc[4][4][4];
    #pragma unroll
    for (int a = 0; a < 4; ++a)
        #pragma unroll
        for (int b = 0; b < 4; ++b)
            #pragma unroll
            for (int q = 0; q < 4; ++q) acc[a][b][q] = 0.f;

    {
        #pragma unroll
        for (int i = 0; i < 8; ++i) {
            int idx = tid + i*256;
            int arr = idx >> 9, r = (idx >> 2) & 127, v = idx & 3;
            uint32_t dst = sbase + (uint32_t)(arr*TILE_H + r*LDSH + v*8)*2;
            CP_ASYNC16(dst, gp[arr] + (size_t)r*K + v*8);
        }
        CP_COMMIT();
    }
    for (int c = 0; c < NC; ++c) {
        if (c + 1 < NC) {
            int s = (c+1) & 1;
            #pragma unroll
            for (int i = 0; i < 8; ++i) {
                int idx = tid + i*256;
                int arr = idx >> 9, r = (idx >> 2) & 127, v = idx & 3;
                uint32_t dst = sbase + (uint32_t)(s*STAGE_H + arr*TILE_H + r*LDSH + v*8)*2;
                CP_ASYNC16(dst, gp[arr] + (size_t)r*K + (c+1)*32 + v*8);
            }
            CP_COMMIT();
            CP_WAIT(1);
        } else {
            CP_WAIT(0);
        }
        __syncthreads();
        uint32_t stg = sbase + (uint32_t)((c & 1)*STAGE_H)*2;
        #pragma unroll
        for (int kh2 = 0; kh2 < 2; ++kh2) {
            int ks = kh2*16;
            uint32_t ah[4][4], al[4][4], bh[4][2], bl[4][2];
            #pragma unroll
            for (int mt = 0; mt < 4; ++mt) {
                int row = wrow*64 + mt*16 + (lane & 15);
                uint32_t off = (uint32_t)(row*LDSH + ks + (lane >> 4)*8)*2;
                ldsm4(ah[mt], stg + off);
                ldsm4(al[mt], stg + (uint32_t)TILE_H*2 + off);
            }
            #pragma unroll
            for (int nt = 0; nt < 4; ++nt) {
                int l4 = lane & 15;
                int nr = wcol*32 + nt*8 + (l4 & 7);
                uint32_t off = (uint32_t)(nr*LDSH + ks + (l4 >> 3)*8)*2;
                ldsm2(bh[nt], stg + (uint32_t)(2*TILE_H)*2 + off);
                ldsm2(bl[nt], stg + (uint32_t)(3*TILE_H)*2 + off);
            }
            #pragma unroll
            for (int mt = 0; mt < 4; ++mt)
                #pragma unroll
                for (int nt = 0; nt < 4; ++nt)
                    mma16816(acc[mt][nt], ah[mt], bh[nt]);
            #pragma unroll
            for (int mt = 0; mt < 4; ++mt)
                #pragma unroll
                for (int nt = 0; nt < 4; ++nt)
                    mma16816(acc[mt][nt], ah[mt], bl[nt]);
            #pragma unroll
            for (int mt = 0; mt < 4; ++mt)
                #pragma unroll
                for (int nt = 0; nt < 4; ++nt)
                    mma16816(acc[mt][nt], al[mt], bh[nt]);
        }
        __syncthreads();
    }

    int group = lane >> 2, tig = lane & 3;
    #pragma unroll
    for (int mt = 0; mt < 4; ++mt)
        #pragma unroll
        for (int nt = 0; nt < 4; ++nt) {
            int r = m0 + wrow*64 + mt*16 + group;
            int cc = n0 + wcol*32 + nt*8 + tig*2;
            float b0 = bias[cc], b1 = bias[cc+1];
            #pragma unroll
            for (int half = 0; half < 2; ++half) {
                int rr = r + half*8;
                float v0 = acc[mt][nt][half*2+0] + b0;
                float v1 = acc[mt][nt][half*2+1] + b1;
                if (EPI == 1) {
                    v0 = fmaxf(v0, 0.f); v1 = fmaxf(v1, 0.f);
                    __half h0, l0, h1, l1;
                    split2h(v0, h0, l0); split2h(v1, h1, l1);
                    *(__half2*)(Ch + (size_t)rr*N + cc) = __halves2half2(h0, h1);
                    *(__half2*)(Cl + (size_t)rr*N + cc) = __halves2half2(l0, l1);
                } else {
                    if (EPI == 2) {
                        float2 r2 = *(const float2*)(res + (size_t)rr*N + cc);
                        v0 += r2.x; v1 += r2.y;
                    }
                    float2 o; o.x = v0; o.y = v1;
                    *(float2*)(Cf + (size_t)rr*N + cc) = o;
                }
            }
        }
}

// ======== counter zeroing (4096 counters) ========
__global__ void zero_cnt_kernel(unsigned* __restrict__ c) {
    c[blockIdx.x * blockDim.x + threadIdx.x] = 0u;
}

// ======== persistent GRU v5: batch-grouped (8b x 16u per CTA, 16-way sync) ======
// smem: w [48 rows][264] (k halves at +0/+132), h [8 b][264]
#define GRU_SMEM ((48*264 + 8*264) * 4)
__global__ __launch_bounds__(256)
void gru_persistent(const float* __restrict__ gi0, const float* __restrict__ gi1,
                    float* __restrict__ hcat,
                    __half* __restrict__ hch, __half* __restrict__ hcl,
                    const float* __restrict__ whhF, const float* __restrict__ whhB,
                    const float* __restrict__ bhhF, const float* __restrict__ bhhB,
                    unsigned* __restrict__ cnt,
                    const float* __restrict__ ff_w1, const float* __restrict__ ff_w2,
                    __half* __restrict__ w1h, __half* __restrict__ w1l,
                    __half* __restrict__ w2h, __half* __restrict__ w2l) {
    extern __shared__ float sm[];
    int tid = threadIdx.x;

    if (blockIdx.x >= 128) {
        // ---- FF weight transpose+split (concurrent) ----
        float* tsm = sm;
        int tx = tid & 31, ty8 = tid >> 5;
        int cid = blockIdx.x - 128;
        for (int tile = cid; tile < 8192; tile += 128) {
            int blk = tile >> 11, rem = tile & 2047;
            const float* in; __half *oh, *ol; int R, C, t2;
            if (rem < 1024) {
                size_t wo = (size_t)blk*Dd*DFFv;
                in = ff_w1 + wo; oh = w1h + wo; ol = w1l + wo;
                R = Dd; C = DFFv; t2 = rem;
            } else {
                size_t wo = (size_t)blk*DFFv*Dd;
                in = ff_w2 + wo; oh = w2h + wo; ol = w2l + wo;
                R = DFFv; C = Dd; t2 = rem - 1024;
            }
            int ntx = C >> 5;
            int c0 = (t2 % ntx) << 5, r0 = (t2 / ntx) << 5;
            #pragma unroll
            for (int i = 0; i < 32; i += 8)
                tsm[(ty8 + i)*33 + tx] = in[(size_t)(r0 + ty8 + i)*C + c0 + tx];
            __syncthreads();
            #pragma unroll
            for (int i = 0; i < 32; i += 8) {
                __half h, l;
                split2h(tsm[tx*33 + ty8 + i], h, l);
                size_t o = (size_t)(c0 + ty8 + i)*R + r0 + tx;
                oh[o] = h; ol[o] = l;
            }
            __syncthreads();
        }
        return;
    }

    // ---- GRU: id = dir(1) | grp(2) | ucta(4) ----
    float* w_s = sm;              // 48 rows x 264
    float* h_s = sm + 48*264;     // 8 b x 264
    int dir = blockIdx.x >> 6;
    int grp = (blockIdx.x >> 4) & 3;
    int ucta = blockIdx.x & 15;
    const float* gi  = dir ? gi1  : gi0;
    const float* whh = dir ? whhB : whhF;
    const float* bhh = dir ? bhhB : bhhF;
    unsigned* mycnt = cnt + ((size_t)(dir*4 + grp))*Tt;
    int jbase = ucta * 16;
    int bg = grp * 8;

    // stage 48 weight rows (16 units x 3 gates), halves at +0/+132
    for (int i = tid; i < 48*64; i += 256) {
        int lr = i >> 6, k4 = i & 63;
        int jl = lr / 3, g = lr % 3;
        float4 wv = *(const float4*)(whh + (size_t)(g*Hh + jbase + jl)*Hh + k4*4);
        *(float4*)&w_s[lr*264 + (k4 >> 5)*132 + (k4 & 31)*4] = wv;
    }
    int lane = tid & 31, w = tid >> 5;
    int kh = lane & 1;                       // k half
    int b_l = (lane >> 1) & 7;               // local batch 0..7
    int jl = w*2 + (lane >> 4);              // local unit 0..15
    int j = jbase + jl;
    int b = bg + b_l;
    float brr = bhh[j], bz = bhh[256 + j], bn_ = bhh[512 + j];
    const float* wr = w_s + (jl*3 + 0)*264 + kh*132;
    const float* wz = w_s + (jl*3 + 1)*264 + kh*132;
    const float* wn = w_s + (jl*3 + 2)*264 + kh*132;
    __syncthreads();

    for (int s = 0; s < Tt; ++s) {
        int t = dir ? (Tt - 1 - s) : s;
        const float* gib = gi + (size_t)t*Bb*768 + (size_t)b*768;
        float g_r = gib[j], g_z = gib[256 + j], g_n = gib[512 + j];
        const float* hp = nullptr;
        if (s > 0)
            hp = dir ? (hcat + (size_t)(t+1)*Bb*Dd + Hh) : (hcat + (size_t)(t-1)*Bb*Dd);
        if (hp) {
            for (int i = tid; i < 8*64; i += 256) {
                int bb = i >> 6, k4 = i & 63;
                float4 hv = *(const float4*)(hp + (size_t)(bg + bb)*Dd + k4*4);
                *(float4*)&h_s[bb*264 + (k4 >> 5)*132 + (k4 & 31)*4] = hv;
            }
        } else {
            for (int i = tid; i < 8*264; i += 256) h_s[i] = 0.f;
        }
        __syncthreads();

        const float* hb = h_s + b_l*264 + kh*132;
        float ar = 0.f, az = 0.f, an = 0.f;
        #pragma unroll 8
        for (int k4 = 0; k4 < 32; ++k4) {
            float4 h4  = *(const float4*)(hb + k4*4);
            float4 w_r = *(const float4*)(wr + k4*4);
            float4 w_z = *(const float4*)(wz + k4*4);
            float4 w_n = *(const float4*)(wn + k4*4);
            ar += w_r.x*h4.x + w_r.y*h4.y + w_r.z*h4.z + w_r.w*h4.w;
            az += w_z.x*h4.x + w_z.y*h4.y + w_z.z*h4.z + w_z.w*h4.w;
            an += w_n.x*h4.x + w_n.y*h4.y + w_n.z*h4.z + w_n.w*h4.w;
        }
        ar += __shfl_xor_sync(0xffffffffu, ar, 1);
        az += __shfl_xor_sync(0xffffffffu, az, 1);
        an += __shfl_xor_sync(0xffffffffu, an, 1);

        if (kh == 0) {
            float hprev_v = h_s[b_l*264 + (j >> 7)*132 + (j & 127)];
            float r = 1.f / (1.f + expf(-(g_r + ar + brr)));
            float z = 1.f / (1.f + expf(-(g_z + az + bz)));
            float n = tanhf(g_n + r*(an + bn_));
            float hv = (1.f - z)*n + z*hprev_v;
            size_t oo = (size_t)t*Bb*Dd + (size_t)b*Dd + dir*Hh + j;
            hcat[oo] = hv;
            __half hh, hl;
            split2h(hv, hh, hl);
            hch[oo] = hh; hcl[oo] = hl;
        }

        __syncthreads();
        if (tid == 0) {
            red_release(mycnt + s, 1u);
            while (ld_acquire(mycnt + s) < 16u) { }
        }
        __syncthreads();
    }
}

// ======== LayerNorm + optional fused 2-limb split ========
__global__ __launch_bounds__(128)
void ln_split2_kernel(const float* __restrict__ in, float* __restrict__ out,
                      __half* __restrict__ oh, __half* __restrict__ ol,
                      const float* __restrict__ g, const float* __restrict__ bta) {
    int row = blockIdx.x, tid = threadIdx.x;
    __shared__ float red[4];
    float4 v = *(const float4*)(in + (size_t)row*Dd + tid*4);
    float s = v.x + v.y + v.z + v.w;
    #pragma unroll
    for (int o = 16; o; o >>= 1) s += __shfl_xor_sync(0xffffffffu, s, o);
    if ((tid & 31) == 0) red[tid >> 5] = s;
    __syncthreads();
    float mean = (red[0]+red[1]+red[2]+red[3]) * (1.f/512.f);
    float dx = v.x-mean, dy = v.y-mean, dz = v.z-mean, dw = v.w-mean;
    float q = dx*dx + dy*dy + dz*dz + dw*dw;
    #pragma unroll
    for (int o = 16; o; o >>= 1) q += __shfl_xor_sync(0xffffffffu, q, o);
    __syncthreads();
    if ((tid & 31) == 0) red[tid >> 5] = q;
    __syncthreads();
    float var = (red[0]+red[1]+red[2]+red[3]) * (1.f/512.f);
    float rs = rsqrtf(var + 1e-5f);
    float4 g4 = *(const float4*)(g   + tid*4);
    float4 b4 = *(const float4*)(bta + tid*4);
    float ov[4];
    ov[0] = dx*rs*g4.x + b4.x; ov[1] = dy*rs*g4.y + b4.y;
    ov[2] = dz*rs*g4.z + b4.z; ov[3] = dw*rs*g4.w + b4.w;
    *(float4*)(out + (size_t)row*Dd + tid*4) = *(float4*)ov;
    if (oh) {
        size_t o = (size_t)row*Dd + tid*4;
        #pragma unroll
        for (int qq = 0; qq < 4; ++qq) {
            __half h, l;
            split2h(ov[qq], h, l);
            oh[o+qq] = h; ol[o+qq] = l;
        }
    }
}

// ======== FC ========
__global__ __launch_bounds__(256)
void fc_kernel(const float* __restrict__ A, const float* __restrict__ W,
               const float* __restrict__ bias, float* __restrict__ out) {
    __shared__ float Ws[Dd*Cc];
    int tid = threadIdx.x;
    for (int i = tid; i < Dd*Cc; i += 256) Ws[i] = W[i];
    __syncthreads();
    int r = tid >> 4, c = tid & 15;
    size_t row = (size_t)blockIdx.x*16 + r;
    const float* a = A + row*Dd;
    float acc = bias[c];
    #pragma unroll 4
    for (int k4 = 0; k4 < Dd/4; ++k4) {
        float4 av = *(const float4*)(a + k4*4);
        int kb = k4*4;
        acc += av.x*Ws[(kb+0)*Cc + c] + av.y*Ws[(kb+1)*Cc + c]
             + av.z*Ws[(kb+2)*Cc + c] + av.w*Ws[(kb+3)*Cc + c];
    }
    out[row*Cc + c] = acc;
}

// ======== Viterbi (warp-shuffle, R13 proven) ========
__global__ __launch_bounds__(512)
void viterbi_kernel(const float* __restrict__ logits, const int* __restrict__ y,
                    const float* __restrict__ trans, unsigned char* __restrict__ bp,
                    float* __restrict__ out) {
    __shared__ unsigned char path[32][512];
    __shared__ int tag_s[32];
    __shared__ unsigned ymask[32][16];
    int tid = threadIdx.x;
    int lane = tid & 31;
    int sub = lane >> 4, c = lane & 15;
    int b = ((tid >> 5) << 1) | sub;

    for (int i = tid; i < 32*16; i += 512) {
        int bb = i >> 4, w32 = i & 15;
        unsigned m = 0;
        #pragma unroll 8
        for (int k = 0; k < 32; ++k)
            if (y[(size_t)bb*Tt + w32*32 + k] != 0) m |= (1u << k);
        ymask[bb][w32] = m;
    }
    float trp[16];
    #pragma unroll
    for (int pv = 0; pv < 16; ++pv) trp[pv] = trans[pv*16 + c];
    __syncthreads();

    float score = trans[16 + c] + logits[(size_t)b*16 + c];
    int half = lane & 16;
    for (int t = 1; t < Tt; ++t) {
        float e = logits[(size_t)t*512 + tid];
        float best = -1e30f; int arg = 0;
        #pragma unroll
        for (int pv = 0; pv < 16; ++pv) {
            float sv = __shfl_sync(0xffffffffu, score, half | pv);
            float v = sv + trp[pv];
            if (v > best) { best = v; arg = pv; }
        }
        bool m = (ymask[b][t >> 5] >> (t & 31)) & 1u;
        bp[(size_t)(t-1)*512 + tid] = (unsigned char)arg;
        score = m ? (best + e) : score;
    }
    float fin = score + trans[c*16 + 2];
    float best = -1e30f; int arg = 0;
    #pragma unroll
    for (int k = 0; k < 16; ++k) {
        float v = __shfl_sync(0xffffffffu, fin, half | k);
        if (v > best) { best = v; arg = k; }
    }
    if (c == 0) { out[b] = best; tag_s[b] = arg; }
    __syncthreads();
    if (tid < 32) {
        int bb = tid;
        int tag = tag_s[bb];
        for (int i = Tt - 2; i >= 0; --i) {
            path[bb][i+1] = (unsigned char)tag;
            if ((ymask[bb][(i+1) >> 5] >> ((i+1) & 31)) & 1u)
                tag = bp[(size_t)i*512 + bb*16 + tag];
        }
        path[bb][0] = (unsigned char)tag;
    }
    __syncthreads();
    for (int i = tid; i < 32*512; i += 512)
        out[32 + i] = (float)path[i >> 9][i & 511];
}

// ======== launcher ========
extern "C" void kernel_launch(void* const* d_in, const int* in_sizes, int n_in,
                              void* d_out, int out_size) {
    const int*   x      = (const int*)d_in[0];
    const int*   y      = (const int*)d_in[1];
    const float* embedW = (const float*)d_in[2];
    const float* w_ih_f = (const float*)d_in[3];
    const float* w_hh_f = (const float*)d_in[4];
    const float* b_ih_f = (const float*)d_in[5];
    const float* b_hh_f = (const float*)d_in[6];
    const float* w_ih_b = (const float*)d_in[7];
    const float* w_hh_b = (const float*)d_in[8];
    const float* b_ih_b = (const float*)d_in[9];
    const float* b_hh_b = (const float*)d_in[10];
    const float* ff_w1  = (const float*)d_in[11];
    const float* ff_b1  = (const float*)d_in[12];
    const float* ff_w2  = (const float*)d_in[13];
    const float* ff_b2  = (const float*)d_in[14];
    const float* ln_g   = (const float*)d_in[15];
    const float* ln_b   = (const float*)d_in[16];
    const float* fc_w   = (const float*)d_in[17];
    const float* fc_b   = (const float*)d_in[18];
    const float* trans  = (const float*)d_in[19];
    float* out = (float*)d_out;

    float* buf = nullptr;
    cudaGetSymbolAddress((void**)&buf, g_buf);
    float* pe    = buf + OFF_PE;
    float* gi0   = buf + OFF_GI0;
    float* gi1   = buf + OFF_GI1;
    float* hcat  = buf + OFF_HCAT;
    float* tmp   = buf + OFF_TMP;
    float* logit = buf + OFF_LOG;
    unsigned char* bp = (unsigned char*)(buf + OFF_BP);
    unsigned* cnt = (unsigned*)(buf + OFF_CNT);
    __half* h0h = (__half*)(buf + OFF_H0H);
    __half* h0l = (__half*)(buf + OFF_H0L);
    __half* hch = (__half*)(buf + OFF_HCH);
    __half* hcl = (__half*)(buf + OFF_HCL);
    __half* mdh = (__half*)(buf + OFF_MDH);
    __half* mdl = (__half*)(buf + OFF_MDL);
    __half* w1h = (__half*)(buf + OFF_W1H);
    __half* w1l = (__half*)(buf + OFF_W1L);
    __half* w2h = (__half*)(buf + OFF_W2H);
    __half* w2l = (__half*)(buf + OFF_W2L);
    __half* wfh = (__half*)(buf + OFF_WFH);
    __half* wfl = (__half*)(buf + OFF_WFL);
    __half* wbh = (__half*)(buf + OFF_WBH);
    __half* wbl = (__half*)(buf + OFF_WBL);

    cudaFuncSetAttribute(gru_persistent, cudaFuncAttributeMaxDynamicSharedMemorySize, GRU_SMEM);
    cudaFuncSetAttribute(mma_gemm<0>, cudaFuncAttributeMaxDynamicSharedMemorySize, MMA_SMEM);
    cudaFuncSetAttribute(mma_gemm<1>, cudaFuncAttributeMaxDynamicSharedMemorySize, MMA_SMEM);
    cudaFuncSetAttribute(mma_gemm<2>, cudaFuncAttributeMaxDynamicSharedMemorySize, MMA_SMEM);

    pe_kernel<<<(Tt*Ee + 255)/256, 256>>>(pe);
    embed2_kernel<<<(Mm*(Ee/4) + 255)/256, 256>>>(h0h, h0l, embedW, x, pe);
    conv2_kernel<<<(768*Ee/4 + 255)/256, 256>>>(w_ih_f, wfh, wfl, 768*Ee/4);
    mma_gemm<0><<<dim3(768/128, Mm/128), 256, MMA_SMEM>>>(
        h0h, h0l, wfh, wfl, b_ih_f, nullptr, gi0, nullptr, nullptr, Mm, 768, Ee);
    conv2_kernel<<<(768*Ee/4 + 255)/256, 256>>>(w_ih_b, wbh, wbl, 768*Ee/4);
    mma_gemm<0><<<dim3(768/128, Mm/128), 256, MMA_SMEM>>>(
        h0h, h0l, wbh, wbl, b_ih_b, nullptr, gi1, nullptr, nullptr, Mm, 768, Ee);

    zero_cnt_kernel<<<16, 256>>>(cnt);
    gru_persistent<<<256, 256, GRU_SMEM>>>(gi0, gi1, hcat, hch, hcl,
                                           w_hh_f, w_hh_b, b_hh_f, b_hh_b, cnt,
                                           ff_w1, ff_w2, w1h, w1l, w2h, w2l);

    for (int i = 0; i < 4; ++i) {
        size_t wo1 = (size_t)i*Dd*DFFv, wo2 = (size_t)i*DFFv*Dd;
        mma_gemm<1><<<dim3(DFFv/128, Mm/128), 256, MMA_SMEM>>>(
            hch, hcl, w1h + wo1, w1l + wo1, ff_b1 + (size_t)i*DFFv, nullptr,
            nullptr, mdh, mdl, Mm, DFFv, Dd);
        mma_gemm<2><<<dim3(Dd/128, Mm/128), 256, MMA_SMEM>>>(
            mdh, mdl, w2h + wo2, w2l + wo2, ff_b2 + (size_t)i*Dd, hcat,
            tmp, nullptr, nullptr, Mm, Dd, DFFv);
        bool last = (i == 3);
        ln_split2_kernel<<<Mm, 128>>>(tmp, hcat,
                                      last ? nullptr : hch, last ? nullptr : hcl,
                                      ln_g + (size_t)i*Dd, ln_b + (size_t)i*Dd);
    }

    fc_kernel<<<Mm/16, 256>>>(hcat, fc_w, fc_b, logit);
    viterbi_kernel<<<1, 512>>>(logit, y, trans, bp, out);
}

// round 15
// speedup vs baseline: 1.3613x; 1.0042x over previous
#include <cuda_runtime.h>
#include <cuda_fp16.h>
#include <cstdint>
#include <math.h>

#define Tt 512
#define Bb 32
#define Ee 512
#define Hh 256
#define Dd 512
#define DFFv 2048
#define Cc 16
#define Mm (Tt*Bb)

__device__ __forceinline__ uint32_t smem_u32(const void* p) {
    uint32_t a;
    asm("{ .reg .u64 t; cvta.to.shared.u64 t, %1; cvt.u32.u64 %0, t; }" : "=r"(a) : "l"(p));
    return a;
}
__device__ __forceinline__ void mma16816(float* c, const uint32_t* a, const uint32_t* b) {
    asm volatile("mma.sync.aligned.m16n8k16.row.col.f32.f16.f16.f32 "
        "{%0,%1,%2,%3}, {%4,%5,%6,%7}, {%8,%9}, {%0,%1,%2,%3};"
        : "+f"(c[0]), "+f"(c[1]), "+f"(c[2]), "+f"(c[3])
        : "r"(a[0]), "r"(a[1]), "r"(a[2]), "r"(a[3]), "r"(b[0]), "r"(b[1]));
}
__device__ __forceinline__ void ldsm4(uint32_t* r, uint32_t addr) {
    asm volatile("ldmatrix.sync.aligned.m8n8.x4.shared.b16 {%0,%1,%2,%3}, [%4];"
        : "=r"(r[0]), "=r"(r[1]), "=r"(r[2]), "=r"(r[3]) : "r"(addr));
}
__device__ __forceinline__ void ldsm2(uint32_t* r, uint32_t addr) {
    asm volatile("ldmatrix.sync.aligned.m8n8.x2.shared.b16 {%0,%1}, [%2];"
        : "=r"(r[0]), "=r"(r[1]) : "r"(addr));
}
#define CP_ASYNC16(dst, src) \
    asm volatile("cp.async.cg.shared.global [%0], [%1], 16;" :: "r"(dst), "l"(src))
#define CP_COMMIT() asm volatile("cp.async.commit_group;")
#define CP_WAIT(n)  asm volatile("cp.async.wait_group %0;" :: "n"(n) : "memory")

__device__ __forceinline__ void split2h(float v, __half& h, __half& l) {
    h = __float2half_rn(v);
    l = __float2half_rn(v - __half2float(h));
}
__device__ __forceinline__ void red_release(unsigned* p, unsigned v) {
    asm volatile("red.release.gpu.global.add.u32 [%0], %1;" :: "l"(p), "r"(v) : "memory");
}
__device__ __forceinline__ unsigned ld_acquire(const unsigned* p) {
    unsigned v;
    asm volatile("ld.acquire.gpu.global.u32 %0, [%1];" : "=r"(v) : "l"(p) : "memory");
    return v;
}

// ======== scratch carve-out ========
constexpr size_t AL64(size_t x) { return (x + 63) & ~(size_t)63; }
constexpr size_t SZ_PE = (size_t)Tt*Ee;
constexpr size_t SZ_GI = (size_t)Mm*3*Hh, SZ_HC = (size_t)Mm*Dd;
constexpr size_t SZ_LOG = (size_t)Mm*Cc, SZ_BPF = AL64(((size_t)(Tt-1)*Bb*Cc + 3)/4);
constexpr size_t SZ_H0S = (size_t)Mm*Ee/2, SZ_HCS = (size_t)Mm*Dd/2, SZ_MDS = (size_t)Mm*DFFv/2;
constexpr size_t SZ_W1S = (size_t)4*Dd*DFFv/2, SZ_W2S = (size_t)4*DFFv*Dd/2, SZ_WIS = (size_t)3*Hh*Ee/2;
constexpr size_t OFF_PE  = 0;
constexpr size_t OFF_GI0 = AL64(OFF_PE + SZ_PE);
constexpr size_t OFF_GI1 = AL64(OFF_GI0 + SZ_GI);
constexpr size_t OFF_HCAT= AL64(OFF_GI1 + SZ_GI);
constexpr size_t OFF_TMP = AL64(OFF_HCAT + SZ_HC);
constexpr size_t OFF_LOG = AL64(OFF_TMP + SZ_HC);
constexpr size_t OFF_BP  = AL64(OFF_LOG + SZ_LOG);
constexpr size_t OFF_CNT = AL64(OFF_BP + SZ_BPF);          // 4096 u32
constexpr size_t OFF_H0H = AL64(OFF_CNT + 4096);
constexpr size_t OFF_H0L = AL64(OFF_H0H + SZ_H0S);
constexpr size_t OFF_HCH = AL64(OFF_H0L + SZ_H0S);
constexpr size_t OFF_HCL = AL64(OFF_HCH + SZ_HCS);
constexpr size_t OFF_MDH = AL64(OFF_HCL + SZ_HCS);
constexpr size_t OFF_MDL = AL64(OFF_MDH + SZ_MDS);
constexpr size_t OFF_W1H = AL64(OFF_MDL + SZ_MDS);
constexpr size_t OFF_W1L = AL64(OFF_W1H + SZ_W1S);
constexpr size_t OFF_W2H = AL64(OFF_W1L + SZ_W1S);
constexpr size_t OFF_W2L = AL64(OFF_W2H + SZ_W2S);
constexpr size_t OFF_WFH = AL64(OFF_W2L + SZ_W2S);
constexpr size_t OFF_WFL = AL64(OFF_WFH + SZ_WIS);
constexpr size_t OFF_WBH = AL64(OFF_WFL + SZ_WIS);
constexpr size_t OFF_WBL = AL64(OFF_WBH + SZ_WIS);
constexpr size_t TOTAL_F = AL64(OFF_WBL + SZ_WIS);

__device__ __align__(256) float g_buf[TOTAL_F];

// ======== positional encoding table ========
__global__ void pe_kernel(float* __restrict__ pe) {
    int idx = blockIdx.x * blockDim.x + threadIdx.x;
    if (idx >= Tt*Ee) return;
    int t = idx >> 9, e = idx & 511, i2 = e & ~1;
    double div = exp(-log(10000.0) * (double)i2 / (double)Ee);
    double a = (double)t * div;
    pe[idx] = (float)((e & 1) ? cos(a) : sin(a));
}

// ======== embedding + pe -> 2-limb fp16 ========
__global__ __launch_bounds__(256)
void embed2_kernel(__half* __restrict__ oh, __half* __restrict__ ol,
                   const float* __restrict__ emb, const int* __restrict__ x,
                   const float* __restrict__ pe) {
    int idx = blockIdx.x * blockDim.x + threadIdx.x;
    if (idx >= Mm * (Ee/4)) return;
    int row = idx >> 7, e4 = idx & 127;
    int t = row >> 5, b = row & 31;
    int tok = x[(size_t)b*Tt + t];
    float4 ev = *(const float4*)(emb + (size_t)tok*Ee + e4*4);
    float4 pv = *(const float4*)(pe  + (size_t)t*Ee  + e4*4);
    float v[4] = {ev.x+pv.x, ev.y+pv.y, ev.z+pv.z, ev.w+pv.w};
    size_t o = (size_t)row*Ee + e4*4;
    #pragma unroll
    for (int q = 0; q < 4; ++q) { __half h, l; split2h(v[q], h, l); oh[o+q] = h; ol[o+q] = l; }
}

// ======== dual elementwise fp32 -> 2 limbs (grid.y selects source) ========
__global__ void conv2_dual_kernel(const float* __restrict__ inA, __half* __restrict__ ohA,
                                  __half* __restrict__ olA,
                                  const float* __restrict__ inB, __half* __restrict__ ohB,
                                  __half* __restrict__ olB, int n4) {
    const float* in = blockIdx.y ? inB : inA;
    __half* oh = blockIdx.y ? ohB : ohA;
    __half* ol = blockIdx.y ? olB : olA;
    int idx = blockIdx.x * blockDim.x + threadIdx.x;
    if (idx >= n4) return;
    float4 v4 = *(const float4*)(in + (size_t)idx*4);
    float v[4] = {v4.x, v4.y, v4.z, v4.w};
    size_t o = (size_t)idx*4;
    #pragma unroll
    for (int q = 0; q < 4; ++q) { __half h, l; split2h(v[q], h, l); oh[o+q] = h; ol[o+q] = l; }
}

// ======== fp16 2-limb MMA GEMM (grid.z selects B/bias/out pair) ========
#define LDSH 40
#define TILE_H (128*LDSH)
#define STAGE_H (4*TILE_H)
#define MMA_SMEM (2*STAGE_H*2)

template<int EPI>
__global__ __launch_bounds__(256)
void mma_gemm(const __half* __restrict__ Ah, const __half* __restrict__ Al,
              const __half* __restrict__ Bh, const __half* __restrict__ Bl,
              const __half* __restrict__ Bh2, const __half* __restrict__ Bl2,
              const float* __restrict__ bias, const float* __restrict__ bias2,
              const float* __restrict__ res,
              float* __restrict__ Cf, float* __restrict__ Cf2,
              __half* __restrict__ Ch, __half* __restrict__ Cl,
              int M, int N, int K) {
    if (blockIdx.z) { Bh = Bh2; Bl = Bl2; bias = bias2; Cf = Cf2; }
    extern __shared__ __half sh[];
    int tid = threadIdx.x, lane = tid & 31, wid = tid >> 5;
    int m0 = blockIdx.y * 128, n0 = blockIdx.x * 128;
    int wrow = wid & 1, wcol = wid >> 1;
    const __half* gp[4] = {Ah + (size_t)m0*K, Al + (size_t)m0*K,
                           Bh + (size_t)n0*K, Bl + (size_t)n0*K};
    uint32_t sbase = smem_u32(sh);
    int NC = K >> 5;

    float acc[4][4][4];
    #pragma unroll
    for (int a = 0; a < 4; ++a)
        #pragma unroll
        for (int b = 0; b < 4; ++b)
            #pragma unroll
            for (int q = 0; q < 4; ++q) acc[a][b][q] = 0.f;

    {
        #pragma unroll
        for (int i = 0; i < 8; ++i) {
            int idx = tid + i*256;
            int arr = idx >> 9, r = (idx >> 2) & 127, v = idx & 3;
            uint32_t dst = sbase + (uint32_t)(arr*TILE_H + r*LDSH + v*8)*2;
            CP_ASYNC16(dst, gp[arr] + (size_t)r*K + v*8);
        }
        CP_COMMIT();
    }
    for (int c = 0; c < NC; ++c) {
        if (c + 1 < NC) {
            int s = (c+1) & 1;
            #pragma unroll
            for (int i = 0; i < 8; ++i) {
                int idx = tid + i*256;
                int arr = idx >> 9, r = (idx >> 2) & 127, v = idx & 3;
                uint32_t dst = sbase + (uint32_t)(s*STAGE_H + arr*TILE_H + r*LDSH + v*8)*2;
                CP_ASYNC16(dst, gp[arr] + (size_t)r*K + (c+1)*32 + v*8);
            }
            CP_COMMIT();
            CP_WAIT(1);
        } else {
            CP_WAIT(0);
        }
        __syncthreads();
        uint32_t stg = sbase + (uint32_t)((c & 1)*STAGE_H)*2;
        #pragma unroll
        for (int kh2 = 0; kh2 < 2; ++kh2) {
            int ks = kh2*16;
            uint32_t ah[4][4], al[4][4], bh[4][2], bl[4][2];
            #pragma unroll
            for (int mt = 0; mt < 4; ++mt) {
                int row = wrow*64 + mt*16 + (lane & 15);
                uint32_t off = (uint32_t)(row*LDSH + ks + (lane >> 4)*8)*2;
                ldsm4(ah[mt], stg + off);
                ldsm4(al[mt], stg + (uint32_t)TILE_H*2 + off);
            }
            #pragma unroll
            for (int nt = 0; nt < 4; ++nt) {
                int l4 = lane & 15;
                int nr = wcol*32 + nt*8 + (l4 & 7);
                uint32_t off = (uint32_t)(nr*LDSH + ks + (l4 >> 3)*8)*2;
                ldsm2(bh[nt], stg + (uint32_t)(2*TILE_H)*2 + off);
                ldsm2(bl[nt], stg + (uint32_t)(3*TILE_H)*2 + off);
            }
            #pragma unroll
            for (int mt = 0; mt < 4; ++mt)
                #pragma unroll
                for (int nt = 0; nt < 4; ++nt)
                    mma16816(acc[mt][nt], ah[mt], bh[nt]);
            #pragma unroll
            for (int mt = 0; mt < 4; ++mt)
                #pragma unroll
                for (int nt = 0; nt < 4; ++nt)
                    mma16816(acc[mt][nt], ah[mt], bl[nt]);
            #pragma unroll
            for (int mt = 0; mt < 4; ++mt)
                #pragma unroll
                for (int nt = 0; nt < 4; ++nt)
                    mma16816(acc[mt][nt], al[mt], bh[nt]);
        }
        __syncthreads();
    }

    int group = lane >> 2, tig = lane & 3;
    #pragma unroll
    for (int mt = 0; mt < 4; ++mt)
        #pragma unroll
        for (int nt = 0; nt < 4; ++nt) {
            int r = m0 + wrow*64 + mt*16 + group;
            int cc = n0 + wcol*32 + nt*8 + tig*2;
            float b0 = bias[cc], b1 = bias[cc+1];
            #pragma unroll
            for (int half = 0; half < 2; ++half) {
                int rr = r + half*8;
                float v0 = acc[mt][nt][half*2+0] + b0;
                float v1 = acc[mt][nt][half*2+1] + b1;
                if (EPI == 1) {
                    v0 = fmaxf(v0, 0.f); v1 = fmaxf(v1, 0.f);
                    __half h0, l0, h1, l1;
                    split2h(v0, h0, l0); split2h(v1, h1, l1);
                    *(__half2*)(Ch + (size_t)rr*N + cc) = __halves2half2(h0, h1);
                    *(__half2*)(Cl + (size_t)rr*N + cc) = __halves2half2(l0, l1);
                } else {
                    if (EPI == 2) {
                        float2 r2 = *(const float2*)(res + (size_t)rr*N + cc);
                        v0 += r2.x; v1 += r2.y;
                    }
                    float2 o; o.x = v0; o.y = v1;
                    *(float2*)(Cf + (size_t)rr*N + cc) = o;
                }
            }
        }
}

// ======== counter zeroing ========
__global__ void zero_cnt_kernel(unsigned* __restrict__ c) {
    c[blockIdx.x * blockDim.x + threadIdx.x] = 0u;
}

// ======== persistent GRU v5 (R14 proven) + concurrent FF conversion ========
#define GRU_SMEM ((48*264 + 8*264) * 4)
__global__ __launch_bounds__(256)
void gru_persistent(const float* __restrict__ gi0, const float* __restrict__ gi1,
                    float* __restrict__ hcat,
                    __half* __restrict__ hch, __half* __restrict__ hcl,
                    const float* __restrict__ whhF, const float* __restrict__ whhB,
                    const float* __restrict__ bhhF, const float* __restrict__ bhhB,
                    unsigned* __restrict__ cnt,
                    const float* __restrict__ ff_w1, const float* __restrict__ ff_w2,
                    __half* __restrict__ w1h, __half* __restrict__ w1l,
                    __half* __restrict__ w2h, __half* __restrict__ w2l) {
    extern __shared__ float sm[];
    int tid = threadIdx.x;

    if (blockIdx.x >= 128) {
        float* tsm = sm;
        int tx = tid & 31, ty8 = tid >> 5;
        int cid = blockIdx.x - 128;
        for (int tile = cid; tile < 8192; tile += 128) {
            int blk = tile >> 11, rem = tile & 2047;
            const float* in; __half *oh, *ol; int R, C, t2;
            if (rem < 1024) {
                size_t wo = (size_t)blk*Dd*DFFv;
                in = ff_w1 + wo; oh = w1h + wo; ol = w1l + wo;
                R = Dd; C = DFFv; t2 = rem;
            } else {
                size_t wo = (size_t)blk*DFFv*Dd;
                in = ff_w2 + wo; oh = w2h + wo; ol = w2l + wo;
                R = DFFv; C = Dd; t2 = rem - 1024;
            }
            int ntx = C >> 5;
            int c0 = (t2 % ntx) << 5, r0 = (t2 / ntx) << 5;
            #pragma unroll
            for (int i = 0; i < 32; i += 8)
                tsm[(ty8 + i)*33 + tx] = in[(size_t)(r0 + ty8 + i)*C + c0 + tx];
            __syncthreads();
            #pragma unroll
            for (int i = 0; i < 32; i += 8) {
                __half h, l;
                split2h(tsm[tx*33 + ty8 + i], h, l);
                size_t o = (size_t)(c0 + ty8 + i)*R + r0 + tx;
                oh[o] = h; ol[o] = l;
            }
            __syncthreads();
        }
        return;
    }

    float* w_s = sm;
    float* h_s = sm + 48*264;
    int dir = blockIdx.x >> 6;
    int grp = (blockIdx.x >> 4) & 3;
    int ucta = blockIdx.x & 15;
    const float* gi  = dir ? gi1  : gi0;
    const float* whh = dir ? whhB : whhF;
    const float* bhh = dir ? bhhB : bhhF;
    unsigned* mycnt = cnt + ((size_t)(dir*4 + grp))*Tt;
    int jbase = ucta * 16;
    int bg = grp * 8;

    for (int i = tid; i < 48*64; i += 256) {
        int lr = i >> 6, k4 = i & 63;
        int jl = lr / 3, g = lr % 3;
        float4 wv = *(const float4*)(whh + (size_t)(g*Hh + jbase + jl)*Hh + k4*4);
        *(float4*)&w_s[lr*264 + (k4 >> 5)*132 + (k4 & 31)*4] = wv;
    }
    int lane = tid & 31, w = tid >> 5;
    int kh = lane & 1;
    int b_l = (lane >> 1) & 7;
    int jl = w*2 + (lane >> 4);
    int j = jbase + jl;
    int b = bg + b_l;
    float brr = bhh[j], bz = bhh[256 + j], bn_ = bhh[512 + j];
    const float* wr = w_s + (jl*3 + 0)*264 + kh*132;
    const float* wz = w_s + (jl*3 + 1)*264 + kh*132;
    const float* wn = w_s + (jl*3 + 2)*264 + kh*132;
    __syncthreads();

    for (int s = 0; s < Tt; ++s) {
        int t = dir ? (Tt - 1 - s) : s;
        const float* gib = gi + (size_t)t*Bb*768 + (size_t)b*768;
        float g_r = gib[j], g_z = gib[256 + j], g_n = gib[512 + j];
        const float* hp = nullptr;
        if (s > 0)
            hp = dir ? (hcat + (size_t)(t+1)*Bb*Dd + Hh) : (hcat + (size_t)(t-1)*Bb*Dd);
        if (hp) {
            for (int i = tid; i < 8*64; i += 256) {
                int bb = i >> 6, k4 = i & 63;
                float4 hv = *(const float4*)(hp + (size_t)(bg + bb)*Dd + k4*4);
                *(float4*)&h_s[bb*264 + (k4 >> 5)*132 + (k4 & 31)*4] = hv;
            }
        } else {
            for (int i = tid; i < 8*264; i += 256) h_s[i] = 0.f;
        }
        __syncthreads();

        const float* hb = h_s + b_l*264 + kh*132;
        float ar = 0.f, az = 0.f, an = 0.f;
        #pragma unroll 8
        for (int k4 = 0; k4 < 32; ++k4) {
            float4 h4  = *(const float4*)(hb + k4*4);
            float4 w_r = *(const float4*)(wr + k4*4);
            float4 w_z = *(const float4*)(wz + k4*4);
            float4 w_n = *(const float4*)(wn + k4*4);
            ar += w_r.x*h4.x + w_r.y*h4.y + w_r.z*h4.z + w_r.w*h4.w;
            az += w_z.x*h4.x + w_z.y*h4.y + w_z.z*h4.z + w_z.w*h4.w;
            an += w_n.x*h4.x + w_n.y*h4.y + w_n.z*h4.z + w_n.w*h4.w;
        }
        ar += __shfl_xor_sync(0xffffffffu, ar, 1);
        az += __shfl_xor_sync(0xffffffffu, az, 1);
        an += __shfl_xor_sync(0xffffffffu, an, 1);

        if (kh == 0) {
            float hprev_v = h_s[b_l*264 + (j >> 7)*132 + (j & 127)];
            float r = 1.f / (1.f + expf(-(g_r + ar + brr)));
            float z = 1.f / (1.f + expf(-(g_z + az + bz)));
            float n = tanhf(g_n + r*(an + bn_));
            float hv = (1.f - z)*n + z*hprev_v;
            size_t oo = (size_t)t*Bb*Dd + (size_t)b*Dd + dir*Hh + j;
            hcat[oo] = hv;
            __half hh, hl;
            split2h(hv, hh, hl);
            hch[oo] = hh; hcl[oo] = hl;
        }

        __syncthreads();
        if (tid == 0) {
            red_release(mycnt + s, 1u);
            while (ld_acquire(mycnt + s) < 16u) { }
        }
        __syncthreads();
    }
}

// ======== LayerNorm + optional fused 2-limb split ========
__global__ __launch_bounds__(128)
void ln_split2_kernel(const float* __restrict__ in, float* __restrict__ out,
                      __half* __restrict__ oh, __half* __restrict__ ol,
                      const float* __restrict__ g, const float* __restrict__ bta) {
    int row = blockIdx.x, tid = threadIdx.x;
    __shared__ float red[4];
    float4 v = *(const float4*)(in + (size_t)row*Dd + tid*4);
    float s = v.x + v.y + v.z + v.w;
    #pragma unroll
    for (int o = 16; o; o >>= 1) s += __shfl_xor_sync(0xffffffffu, s, o);
    if ((tid & 31) == 0) red[tid >> 5] = s;
    __syncthreads();
    float mean = (red[0]+red[1]+red[2]+red[3]) * (1.f/512.f);
    float dx = v.x-mean, dy = v.y-mean, dz = v.z-mean, dw = v.w-mean;
    float q = dx*dx + dy*dy + dz*dz + dw*dw;
    #pragma unroll
    for (int o = 16; o; o >>= 1) q += __shfl_xor_sync(0xffffffffu, q, o);
    __syncthreads();
    if ((tid & 31) == 0) red[tid >> 5] = q;
    __syncthreads();
    float var = (red[0]+red[1]+red[2]+red[3]) * (1.f/512.f);
    float rs = rsqrtf(var + 1e-5f);
    float4 g4 = *(const float4*)(g   + tid*4);
    float4 b4 = *(const float4*)(bta + tid*4);
    float ov[4];
    ov[0] = dx*rs*g4.x + b4.x; ov[1] = dy*rs*g4.y + b4.y;
    ov[2] = dz*rs*g4.z + b4.z; ov[3] = dw*rs*g4.w + b4.w;
    *(float4*)(out + (size_t)row*Dd + tid*4) = *(float4*)ov;
    if (oh) {
        size_t o = (size_t)row*Dd + tid*4;
        #pragma unroll
        for (int qq = 0; qq < 4; ++qq) {
            __half h, l;
            split2h(ov[qq], h, l);
            oh[o+qq] = h; ol[o+qq] = l;
        }
    }
}

// ======== FC ========
__global__ __launch_bounds__(256)
void fc_kernel(const float* __restrict__ A, const float* __restrict__ W,
               const float* __restrict__ bias, float* __restrict__ out) {
    __shared__ float Ws[Dd*Cc];
    int tid = threadIdx.x;
    for (int i = tid; i < Dd*Cc; i += 256) Ws[i] = W[i];
    __syncthreads();
    int r = tid >> 4, c = tid & 15;
    size_t row = (size_t)blockIdx.x*16 + r;
    const float* a = A + row*Dd;
    float acc = bias[c];
    #pragma unroll 4
    for (int k4 = 0; k4 < Dd/4; ++k4) {
        float4 av = *(const float4*)(a + k4*4);
        int kb = k4*4;
        acc += av.x*Ws[(kb+0)*Cc + c] + av.y*Ws[(kb+1)*Cc + c]
             + av.z*Ws[(kb+2)*Cc + c] + av.w*Ws[(kb+3)*Cc + c];
    }
    out[row*Cc + c] = acc;
}

// ======== Viterbi (warp-shuffle) ========
__global__ __launch_bounds__(512)
void viterbi_kernel(const float* __restrict__ logits, const int* __restrict__ y,
                    const float* __restrict__ trans, unsigned char* __restrict__ bp,
                    float* __restrict__ out) {
    __shared__ unsigned char path[32][512];
    __shared__ int tag_s[32];
    __shared__ unsigned ymask[32][16];
    int tid = threadIdx.x;
    int lane = tid & 31;
    int sub = lane >> 4, c = lane & 15;
    int b = ((tid >> 5) << 1) | sub;

    for (int i = tid; i < 32*16; i += 512) {
        int bb = i >> 4, w32 = i & 15;
        unsigned m = 0;
        #pragma unroll 8
        for (int k = 0; k < 32; ++k)
            if (y[(size_t)bb*Tt + w32*32 + k] != 0) m |= (1u << k);
        ymask[bb][w32] = m;
    }
    float trp[16];
    #pragma unroll
    for (int pv = 0; pv < 16; ++pv) trp[pv] = trans[pv*16 + c];
    __syncthreads();

    float score = trans[16 + c] + logits[(size_t)b*16 + c];
    int half = lane & 16;
    for (int t = 1; t < Tt; ++t) {
        float e = logits[(size_t)t*512 + tid];
        float best = -1e30f; int arg = 0;
        #pragma unroll
        for (int pv = 0; pv < 16; ++pv) {
            float sv = __shfl_sync(0xffffffffu, score, half | pv);
            float v = sv + trp[pv];
            if (v > best) { best = v; arg = pv; }
        }
        bool m = (ymask[b][t >> 5] >> (t & 31)) & 1u;
        bp[(size_t)(t-1)*512 + tid] = (unsigned char)arg;
        score = m ? (best + e) : score;
    }
    float fin = score + trans[c*16 + 2];
    float best = -1e30f; int arg = 0;
    #pragma unroll
    for (int k = 0; k < 16; ++k) {
        float v = __shfl_sync(0xffffffffu, fin, half | k);
        if (v > best) { best = v; arg = k; }
    }
    if (c == 0) { out[b] = best; tag_s[b] = arg; }
    __syncthreads();
    if (tid < 32) {
        int bb = tid;
        int tag = tag_s[bb];
        for (int i = Tt - 2; i >= 0; --i) {
            path[bb][i+1] = (unsigned char)tag;
            if ((ymask[bb][(i+1) >> 5] >> ((i+1) & 31)) & 1u)
                tag = bp[(size_t)i*512 + bb*16 + tag];
        }
        path[bb][0] = (unsigned char)tag;
    }
    __syncthreads();
    for (int i = tid; i < 32*512; i += 512)
        out[32 + i] = (float)path[i >> 9][i & 511];
}

// ======== launcher ========
extern "C" void kernel_launch(void* const* d_in, const int* in_sizes, int n_in,
                              void* d_out, int out_size) {
    const int*   x      = (const int*)d_in[0];
    const int*   y      = (const int*)d_in[1];
    const float* embedW = (const float*)d_in[2];
    const float* w_ih_f = (const float*)d_in[3];
    const float* w_hh_f = (const float*)d_in[4];
    const float* b_ih_f = (const float*)d_in[5];
    const float* b_hh_f = (const float*)d_in[6];
    const float* w_ih_b = (const float*)d_in[7];
    const float* w_hh_b = (const float*)d_in[8];
    const float* b_ih_b = (const float*)d_in[9];
    const float* b_hh_b = (const float*)d_in[10];
    const float* ff_w1  = (const float*)d_in[11];
    const float* ff_b1  = (const float*)d_in[12];
    const float* ff_w2  = (const float*)d_in[13];
    const float* ff_b2  = (const float*)d_in[14];
    const float* ln_g   = (const float*)d_in[15];
    const float* ln_b   = (const float*)d_in[16];
    const float* fc_w   = (const float*)d_in[17];
    const float* fc_b   = (const float*)d_in[18];
    const float* trans  = (const float*)d_in[19];
    float* out = (float*)d_out;

    float* buf = nullptr;
    cudaGetSymbolAddress((void**)&buf, g_buf);
    float* pe    = buf + OFF_PE;
    float* gi0   = buf + OFF_GI0;
    float* gi1   = buf + OFF_GI1;
    float* hcat  = buf + OFF_HCAT;
    float* tmp   = buf + OFF_TMP;
    float* logit = buf + OFF_LOG;
    unsigned char* bp = (unsigned char*)(buf + OFF_BP);
    unsigned* cnt = (unsigned*)(buf + OFF_CNT);
    __half* h0h = (__half*)(buf + OFF_H0H);
    __half* h0l = (__half*)(buf + OFF_H0L);
    __half* hch = (__half*)(buf + OFF_HCH);
    __half* hcl = (__half*)(buf + OFF_HCL);
    __half* mdh = (__half*)(buf + OFF_MDH);
    __half* mdl = (__half*)(buf + OFF_MDL);
    __half* w1h = (__half*)(buf + OFF_W1H);
    __half* w1l = (__half*)(buf + OFF_W1L);
    __half* w2h = (__half*)(buf + OFF_W2H);
    __half* w2l = (__half*)(buf + OFF_W2L);
    __half* wfh = (__half*)(buf + OFF_WFH);
    __half* wfl = (__half*)(buf + OFF_WFL);
    __half* wbh = (__half*)(buf + OFF_WBH);
    __half* wbl = (__half*)(buf + OFF_WBL);

    cudaFuncSetAttribute(gru_persistent, cudaFuncAttributeMaxDynamicSharedMemorySize, GRU_SMEM);
    cudaFuncSetAttribute(mma_gemm<0>, cudaFuncAttributeMaxDynamicSharedMemorySize, MMA_SMEM);
    cudaFuncSetAttribute(mma_gemm<1>, cudaFuncAttributeMaxDynamicSharedMemorySize, MMA_SMEM);
    cudaFuncSetAttribute(mma_gemm<2>, cudaFuncAttributeMaxDynamicSharedMemorySize, MMA_SMEM);

    // launches 1-5; launch 6 = gru (ncu capture target)
    pe_kernel<<<(Tt*Ee + 255)/256, 256>>>(pe);                                      // 1
    embed2_kernel<<<(Mm*(Ee/4) + 255)/256, 256>>>(h0h, h0l, embedW, x, pe);         // 2
    conv2_dual_kernel<<<dim3(384, 2), 256>>>(w_ih_f, wfh, wfl,
                                             w_ih_b, wbh, wbl, 768*Ee/4);           // 3
    mma_gemm<0><<<dim3(768/128, Mm/128, 2), 256, MMA_SMEM>>>(
        h0h, h0l, wfh, wfl, wbh, wbl, b_ih_f, b_ih_b, nullptr,
        gi0, gi1, nullptr, nullptr, Mm, 768, Ee);                                   // 4
    zero_cnt_kernel<<<16, 256>>>(cnt);                                              // 5
    gru_persistent<<<256, 256, GRU_SMEM>>>(gi0, gi1, hcat, hch, hcl,
                                           w_hh_f, w_hh_b, b_hh_f, b_hh_b, cnt,
                                           ff_w1, ff_w2, w1h, w1l, w2h, w2l);       // 6

    for (int i = 0; i < 4; ++i) {
        size_t wo1 = (size_t)i*Dd*DFFv, wo2 = (size_t)i*DFFv*Dd;
        mma_gemm<1><<<dim3(DFFv/128, Mm/128), 256, MMA_SMEM>>>(
            hch, hcl, w1h + wo1, w1l + wo1, nullptr, nullptr,
            ff_b1 + (size_t)i*DFFv, nullptr, nullptr,
            nullptr, nullptr, mdh, mdl, Mm, DFFv, Dd);
        mma_gemm<2><<<dim3(Dd/128, Mm/128), 256, MMA_SMEM>>>(
            mdh, mdl, w2h + wo2, w2l + wo2, nullptr, nullptr,
            ff_b2 + (size_t)i*Dd, nullptr, hcat,
            tmp, nullptr, nullptr, nullptr, Mm, Dd, DFFv);
        bool last = (i == 3);
        ln_split2_kernel<<<Mm, 128>>>(tmp, hcat,
                                      last ? nullptr : hch, last ? nullptr : hcl,
                                      ln_g + (size_t)i*Dd, ln_b + (size_t)i*Dd);
    }

    fc_kernel<<<Mm/16, 256>>>(hcat, fc_w, fc_b, logit);
    viterbi_kernel<<<1, 512>>>(logit, y, trans, bp, out);
}